// round 14
// baseline (speedup 1.0000x reference)
#include <cuda_runtime.h>
#include <math_constants.h>

#define BB 16
#define LL 4096
#define HH 8
#define DD 64
#define BH (BB*HH)     // 128
#define UU 45
#define NC 64
#define CLEN 64        // LL/NC

#define TQ 64          // k3: queries padded to 64 for m16 MMA slabs
#define TK 32          // k3: key tile
#define SP 68          // padded smem row stride (64 floats + 4; 16B-aligned rows)
#define SPS 36         // padded stride for the 64x32 score tile
#define NSPLIT 8
#define KS (LL/NSPLIT) // 512 keys per split

#define QT 64          // k1: query tile rows
#define SN 48          // k1: padded sample count (45 real + 3 zero)

// k3 dynamic smem (floats): sQ[TQ*SP], sS[TQ*SPS], sK[2][TK*SP], sV[2][TK*SP]
#define K3_SMEM_FLOATS (TQ*SP + TQ*SPS + 4*TK*SP)
#define K3_SMEM_BYTES  (K3_SMEM_FLOATS*4)
// k1 dynamic smem (floats): sQh, sQl [QT*SP]; sKh, sKl [SN*SP]
#define K1_SMEM_FLOATS ((2*QT + 2*SN)*SP)
#define K1_SMEM_BYTES  (K1_SMEM_FLOATS*4)

typedef unsigned long long u64;
typedef unsigned int u32;

__device__ __forceinline__ void fma2(u64 &d, u64 a, u64 b){
    asm("fma.rn.f32x2 %0, %1, %2, %0;" : "+l"(d) : "l"(a), "l"(b));
}
__device__ __forceinline__ u64 pack2(float x, float y){
    u64 r; asm("mov.b64 %0, {%1, %2};" : "=l"(r) : "f"(x), "f"(y)); return r;
}
__device__ __forceinline__ float2 unpack2(u64 v){
    float2 r; asm("mov.b64 {%0, %1}, %2;" : "=f"(r.x), "=f"(r.y) : "l"(v)); return r;
}
__device__ __forceinline__ void cpa16(unsigned sdst, const void* gsrc){
    asm volatile("cp.async.cg.shared.global [%0], [%1], 16;" :: "r"(sdst), "l"(gsrc));
}
__device__ __forceinline__ void cpa_commit(){
    asm volatile("cp.async.commit_group;");
}
__device__ __forceinline__ u32 f2tf32(float x){
    u32 r; asm("cvt.rna.tf32.f32 %0, %1;" : "=r"(r) : "f"(x)); return r;
}
// m16n8k8 tf32 MMA, D += A*B, accumulate in place
__device__ __forceinline__ void mma_tf32(float4 &d, u32 a0, u32 a1, u32 a2, u32 a3,
                                         u32 b0, u32 b1){
    asm volatile(
        "mma.sync.aligned.m16n8k8.row.col.f32.tf32.tf32.f32 "
        "{%0,%1,%2,%3}, {%4,%5,%6,%7}, {%8,%9}, {%0,%1,%2,%3};"
        : "+f"(d.x), "+f"(d.y), "+f"(d.z), "+f"(d.w)
        : "r"(a0), "r"(a1), "r"(a2), "r"(a3), "r"(b0), "r"(b1));
}

// static scratch (no allocs allowed)
__device__ float g_M[BH*LL];
__device__ int   g_Mtop[BH*UU];
__device__ int   g_rank[BH*LL];
__device__ float g_ctx[BH*UU*DD];
__device__ float g_csum[BH*NC*DD];
__device__ float g_pl[BH*NSPLIT*TQ];
__device__ float g_po[(size_t)BH*NSPLIT*TQ*DD];

// ---------------- K0: init g_rank to -1 ----------------
__global__ __launch_bounds__(256) void k0_rinit()
{
    int4 m1 = make_int4(-1,-1,-1,-1);
    int idx = blockIdx.x * 256 + threadIdx.x;
    #pragma unroll
    for (int t = 0; t < 4; t++)
        ((int4*)g_rank)[idx + t*32768] = m1;
}

// ---------------- K1: M scores via 3xTF32 MMA ----------------
// Per (b,h): M[l] = max_s(Q_l . K2_s) - sum_s(Q_l . K2_s)/L over SN-padded samples.
__global__ __launch_bounds__(256) void k1_M(const float* __restrict__ Q,
                                            const float* __restrict__ K,
                                            const int* __restrict__ idxk, int S)
{
    extern __shared__ __align__(16) float dyn[];
    float* sQh = dyn;                 // QT*SP
    float* sQl = dyn + QT*SP;         // QT*SP
    float* sKh = dyn + 2*QT*SP;       // SN*SP
    float* sKl = dyn + 2*QT*SP + SN*SP;

    __shared__ float pmax[QT][2];
    __shared__ float psum[QT][2];

    int bh = blockIdx.y;
    int b = bh >> 3, h = bh & 7;
    int q0 = blockIdx.x * QT;
    int tid = threadIdx.x;

    // build K2 tile (squared sampled K rows), split hi/lo tf32
    for (int i = tid; i < SN*DD; i += 256) {
        int s = i >> 6, d = i & 63;
        float v = 0.f;
        if (s < S) {
            int kk = idxk[s];
            v = K[(((size_t)b*LL + kk)*HH + h)*DD + d];
        }
        float sq = v * v;
        float hi = __uint_as_float(f2tf32(sq));
        float lo = __uint_as_float(f2tf32(sq - hi));
        sKh[s*SP + d] = hi;
        sKl[s*SP + d] = lo;
    }
    // load Q tile, split hi/lo tf32
    for (int c = tid; c < QT*16; c += 256) {
        int row = c >> 4, dv = c & 15;
        float4 x = ((const float4*)(Q + (((size_t)b*LL + q0 + row)*HH + h)*DD))[dv];
        float4 hi, lo;
        hi.x = __uint_as_float(f2tf32(x.x)); lo.x = __uint_as_float(f2tf32(x.x - hi.x));
        hi.y = __uint_as_float(f2tf32(x.y)); lo.y = __uint_as_float(f2tf32(x.y - hi.y));
        hi.z = __uint_as_float(f2tf32(x.z)); lo.z = __uint_as_float(f2tf32(x.z - hi.z));
        hi.w = __uint_as_float(f2tf32(x.w)); lo.w = __uint_as_float(f2tf32(x.w - hi.w));
        *(float4*)(sQh + row*SP + dv*4) = hi;
        *(float4*)(sQl + row*SP + dv*4) = lo;
    }
    __syncthreads();

    int wid = tid >> 5, lane = tid & 31;
    int slab = wid >> 1, nhalf = wid & 1;   // 4 M-slabs x 2 N-halves
    int g = lane >> 2, tig = lane & 3;
    int rowA = slab*16 + g, rowB = rowA + 8;

    const u32* Qh = (const u32*)sQh;
    const u32* Ql = (const u32*)sQl;
    const u32* Kh = (const u32*)sKh;
    const u32* Kl = (const u32*)sKl;

    float4 dacc[3];
    #pragma unroll
    for (int nt = 0; nt < 3; nt++) dacc[nt] = make_float4(0.f,0.f,0.f,0.f);

    #pragma unroll
    for (int st = 0; st < 8; st++) {
        int ko = st*8;
        u32 ah0 = Qh[rowA*SP + tig + ko],     ah1 = Qh[rowB*SP + tig + ko];
        u32 ah2 = Qh[rowA*SP + tig + 4 + ko], ah3 = Qh[rowB*SP + tig + 4 + ko];
        u32 al0 = Ql[rowA*SP + tig + ko],     al1 = Ql[rowB*SP + tig + ko];
        u32 al2 = Ql[rowA*SP + tig + 4 + ko], al3 = Ql[rowB*SP + tig + 4 + ko];
        #pragma unroll
        for (int nt = 0; nt < 3; nt++) {
            int nrow = nhalf*24 + nt*8 + g;
            int kb = nrow*SP + ko;
            u32 bh0 = Kh[kb + tig], bh1 = Kh[kb + tig + 4];
            u32 bl0 = Kl[kb + tig], bl1 = Kl[kb + tig + 4];
            mma_tf32(dacc[nt], ah0, ah1, ah2, ah3, bh0, bh1);
            mma_tf32(dacc[nt], ah0, ah1, ah2, ah3, bl0, bl1);
            mma_tf32(dacc[nt], al0, al1, al2, al3, bh0, bh1);
        }
    }

    // per-row max (pad cols masked) and sum (pad cols are exact 0)
    float mxA = -CUDART_INF_F, mxB = -CUDART_INF_F;
    float smA = 0.f, smB = 0.f;
    #pragma unroll
    for (int nt = 0; nt < 3; nt++) {
        int c0 = nhalf*24 + nt*8 + 2*tig;
        float4 d = dacc[nt];
        if (c0 < UU)     { mxA = fmaxf(mxA, d.x); mxB = fmaxf(mxB, d.z); }
        if (c0 + 1 < UU) { mxA = fmaxf(mxA, d.y); mxB = fmaxf(mxB, d.w); }
        smA += d.x + d.y;
        smB += d.z + d.w;
    }
    #pragma unroll
    for (int o = 1; o <= 2; o <<= 1) {
        mxA = fmaxf(mxA, __shfl_xor_sync(0xffffffffu, mxA, o));
        mxB = fmaxf(mxB, __shfl_xor_sync(0xffffffffu, mxB, o));
        smA += __shfl_xor_sync(0xffffffffu, smA, o);
        smB += __shfl_xor_sync(0xffffffffu, smB, o);
    }
    if (tig == 0) {
        pmax[slab*16 + g][nhalf] = mxA;      psum[slab*16 + g][nhalf] = smA;
        pmax[slab*16 + g + 8][nhalf] = mxB;  psum[slab*16 + g + 8][nhalf] = smB;
    }
    __syncthreads();
    if (tid < QT) {
        float mx = fmaxf(pmax[tid][0], pmax[tid][1]);
        float sm = psum[tid][0] + psum[tid][1];
        g_M[bh*LL + q0 + tid] = mx - sm * (1.0f / (float)LL);
    }
}

// ---------------- K2 ----------------
__global__ __launch_bounds__(256) void k2_topk()
{
    __shared__ float sM[LL];
    __shared__ float rv[8];
    __shared__ int   ri[8];
    int bh = blockIdx.x;
    for (int i = threadIdx.x; i < LL/4; i += 256)
        ((float4*)sM)[i] = ((const float4*)(g_M + bh*LL))[i];
    __syncthreads();

    int lane = threadIdx.x & 31, wid = threadIdx.x >> 5;
    for (int it = 0; it < UU; it++) {
        float bv = -CUDART_INF_F; int bi = 0x7fffffff;
        for (int i = threadIdx.x; i < LL; i += 256) {
            float v = sM[i];
            if (v > bv || (v == bv && i < bi)) { bv = v; bi = i; }
        }
        #pragma unroll
        for (int o = 16; o > 0; o >>= 1) {
            float ov = __shfl_down_sync(0xffffffffu, bv, o);
            int   oi = __shfl_down_sync(0xffffffffu, bi, o);
            if (ov > bv || (ov == bv && oi < bi)) { bv = ov; bi = oi; }
        }
        if (lane == 0) { rv[wid] = bv; ri[wid] = bi; }
        __syncthreads();
        if (threadIdx.x == 0) {
            for (int w = 1; w < 8; w++)
                if (rv[w] > bv || (rv[w] == bv && ri[w] < bi)) { bv = rv[w]; bi = ri[w]; }
            g_Mtop[bh*UU + it] = bi;
            g_rank[bh*LL + bi] = it;
            sM[bi] = -CUDART_INF_F;
        }
        __syncthreads();
    }
}

// ---------------- K3: split-K flash; QK via tf32 MMA; m=0 softmax ----------------
__global__ __launch_bounds__(256, 3) void k3_attn(const float* __restrict__ Kg,
                                                  const float* __restrict__ Vg,
                                                  const float* __restrict__ Qg)
{
    extern __shared__ __align__(16) float dyn[];
    float* sQ = dyn;                          // TQ*SP
    float* sS = dyn + TQ*SP;                  // TQ*SPS
    float* sK = dyn + TQ*SP + TQ*SPS;         // 2 x TK*SP
    float* sV = sK + 2*TK*SP;                 // 2 x TK*SP

    __shared__ int   s_qi0[TQ];
    __shared__ int   s_qi[TQ];                // sorted DESCENDING
    __shared__ int   s_ou[TQ];
    __shared__ float sLp[TQ*2];               // per-row l partials (2 N-halves)

    int split = blockIdx.y;
    int bh = blockIdx.x;
    int b = bh >> 3, h = bh & 7;
    int tid = threadIdx.x;
    int ks = split * KS;

    if (tid < TQ) s_qi0[tid] = (tid < UU) ? g_Mtop[bh*UU + tid] : -1;
    __syncthreads();
    if (tid < TQ) {
        int qi = s_qi0[tid];
        int r = 0;
        #pragma unroll
        for (int j = 0; j < TQ; j++) {
            int qj = s_qi0[j];
            r += (qj > qi) || (qj == qi && j < tid);   // descending
        }
        s_qi[r] = qi;
        s_ou[r] = tid;
    }
    __syncthreads();
    int maxq = s_qi[0];

    for (int i = tid; i < TQ*16; i += 256) {
        int q = i >> 4, dv = i & 15;
        int row = s_qi[q];
        float4 v = make_float4(0.f, 0.f, 0.f, 0.f);
        if (row >= 0)
            v = ((const float4*)(Qg + (((size_t)b*LL + row)*HH + h)*DD))[dv];
        ((float4*)(sQ + q*SP))[dv] = v;
    }

    // QK MMA warp roles
    int wid2 = tid >> 5, lane = tid & 31;
    int slab = wid2 >> 1;
    int nhalf = wid2 & 1;
    int g = lane >> 2, tig = lane & 3;
    int rowA = slab*16 + g, rowB = rowA + 8;
    int wrow = slab*16 - (slab*16) % 3;

    // PV roles
    int qg = tid >> 4, lg = tid & 15;
    int q0 = qg*3, d0g = lg;

    __syncthreads();
    int qiA = s_qi[rowA], qiB = s_qi[rowB];
    int wqi = s_qi[wrow];
    int pvq = s_qi[q0];

    float l_r[3] = {0.f, 0.f, 0.f};
    u64 o0[3] = {0ull,0ull,0ull}, o1[3] = {0ull,0ull,0ull};

    const float scale = 0.125f;
    int tend = min(ks + KS, maxq + 1);

    int lr = tid >> 4, ldv = tid & 15;
    unsigned sK_s = (unsigned)__cvta_generic_to_shared(sK);
    unsigned sV_s = (unsigned)__cvta_generic_to_shared(sV);
    size_t grow = ((size_t)b*LL)*HH*DD + (size_t)h*DD + ldv*4;

    if (ks < tend) {
        #pragma unroll
        for (int t = 0; t < 2; t++) {
            int r = lr + 16*t;
            size_t go = grow + (size_t)(ks + r)*HH*DD;
            unsigned so = (unsigned)((r*SP + ldv*4)*4);
            cpa16(sK_s + so, Kg + go);
            cpa16(sV_s + so, Vg + go);
        }
        cpa_commit();
    }
    __syncthreads();

    int buf = 0;
    for (int t0 = ks; t0 < tend; t0 += TK, buf ^= 1) {
        int tn = t0 + TK;
        bool more = (tn < tend);

        if (more) {
            unsigned kb = sK_s + (buf^1)*TK*SP*4;
            unsigned vb = sV_s + (buf^1)*TK*SP*4;
            #pragma unroll
            for (int t = 0; t < 2; t++) {
                int r = lr + 16*t;
                size_t go = grow + (size_t)(tn + r)*HH*DD;
                unsigned so = (unsigned)((r*SP + ldv*4)*4);
                cpa16(kb + so, Kg + go);
                cpa16(vb + so, Vg + go);
            }
            cpa_commit();
            asm volatile("cp.async.wait_group 1;");
        } else {
            asm volatile("cp.async.wait_group 0;");
        }
        __syncthreads();

        const float* cK = sK + buf*TK*SP;
        const float* cV = sV + buf*TK*SP;

        // QK via tf32 MMA
        if (wqi >= t0) {
            const u32* sQu = (const u32*)sQ;
            const u32* cKu = (const u32*)cK;
            float4 d0 = make_float4(0.f,0.f,0.f,0.f);
            float4 d1 = make_float4(0.f,0.f,0.f,0.f);
            #pragma unroll
            for (int st = 0; st < 8; st++) {
                int ko = st*8;
                u32 a0 = sQu[rowA*SP + tig + ko];
                u32 a1 = sQu[rowB*SP + tig + ko];
                u32 a2 = sQu[rowA*SP + tig + 4 + ko];
                u32 a3 = sQu[rowB*SP + tig + 4 + ko];
                int kn0 = (nhalf*16 + g)*SP + tig + ko;
                int kn1 = (nhalf*16 + 8 + g)*SP + tig + ko;
                u32 b00 = cKu[kn0],     b01 = cKu[kn0 + 4];
                u32 b10 = cKu[kn1],     b11 = cKu[kn1 + 4];
                mma_tf32(d0, a0, a1, a2, a3, b00, b01);
                mma_tf32(d1, a0, a1, a2, a3, b10, b11);
            }
            float rsumA = 0.f, rsumB = 0.f;
            #pragma unroll
            for (int nt = 0; nt < 2; nt++) {
                float4 d = nt ? d1 : d0;
                int c0 = nhalf*16 + nt*8 + 2*tig;
                int k0g = t0 + c0;
                float pA0 = (k0g   <= qiA) ? __expf(d.x * scale) : 0.f;
                float pA1 = (k0g+1 <= qiA) ? __expf(d.y * scale) : 0.f;
                float pB0 = (k0g   <= qiB) ? __expf(d.z * scale) : 0.f;
                float pB1 = (k0g+1 <= qiB) ? __expf(d.w * scale) : 0.f;
                *(float2*)(sS + rowA*SPS + c0) = make_float2(pA0, pA1);
                *(float2*)(sS + rowB*SPS + c0) = make_float2(pB0, pB1);
                rsumA += pA0 + pA1;
                rsumB += pB0 + pB1;
            }
            rsumA += __shfl_xor_sync(0xffffffffu, rsumA, 1);
            rsumA += __shfl_xor_sync(0xffffffffu, rsumA, 2);
            rsumB += __shfl_xor_sync(0xffffffffu, rsumB, 1);
            rsumB += __shfl_xor_sync(0xffffffffu, rsumB, 2);
            if (tig == 0) {
                sLp[rowA*2 + nhalf] = rsumA;
                sLp[rowB*2 + nhalf] = rsumB;
            }
        }
        __syncthreads();

        // PV (scalar packed FMA)
        if (pvq >= t0) {
            if (lg == 0) {
                #pragma unroll
                for (int j = 0; j < 3; j++)
                    l_r[j] += sLp[(q0+j)*2] + sLp[(q0+j)*2 + 1];
            }
            for (int kb2 = 0; kb2 < TK; kb2 += 4) {
                float4 sv[3];
                #pragma unroll
                for (int j = 0; j < 3; j++)
                    sv[j] = *(const float4*)(sS + (q0+j)*SPS + kb2);
                ulonglong2 vv[4];
                #pragma unroll
                for (int t = 0; t < 4; t++)
                    vv[t] = ((const ulonglong2*)(cV + (kb2+t)*SP))[d0g];
                #pragma unroll
                for (int j = 0; j < 3; j++) {
                    float sj[4] = {sv[j].x, sv[j].y, sv[j].z, sv[j].w};
                    #pragma unroll
                    for (int t = 0; t < 4; t++) {
                        u64 sp = pack2(sj[t], sj[t]);
                        fma2(o0[j], sp, vv[t].x);
                        fma2(o1[j], sp, vv[t].y);
                    }
                }
            }
        }
        __syncthreads();
    }

    // write partials
    int pbase = (bh*NSPLIT + split)*TQ;
    #pragma unroll
    for (int j = 0; j < 3; j++) {
        int q = q0 + j;
        int ou = s_ou[q];
        if (ou < UU) {
            float2 a = unpack2(o0[j]);
            float2 c = unpack2(o1[j]);
            ((float4*)(g_po + ((size_t)(pbase + ou))*DD))[d0g] =
                make_float4(a.x, a.y, c.x, c.y);
            if (lg == 0)
                g_pl[pbase + ou] = l_r[j];
        }
    }
}

// ---------------- K3c: combine split partials (m=0: plain sums) ----------------
__global__ __launch_bounds__(256) void k3c_combine()
{
    __shared__ float sinv[UU];
    int bh = blockIdx.x;
    int tid = threadIdx.x;
    if (tid < UU) {
        float l = 0.f;
        #pragma unroll
        for (int s = 0; s < NSPLIT; s++)
            l += g_pl[(bh*NSPLIT + s)*TQ + tid];
        sinv[tid] = 1.f / l;
    }
    __syncthreads();
    for (int idx = tid; idx < UU*16; idx += 256) {
        int q = idx >> 4, dv = idx & 15;
        float4 acc = make_float4(0.f, 0.f, 0.f, 0.f);
        #pragma unroll
        for (int s = 0; s < NSPLIT; s++) {
            float4 v = ((const float4*)(g_po + ((size_t)((bh*NSPLIT + s)*TQ + q))*DD))[dv];
            acc.x += v.x; acc.y += v.y; acc.z += v.z; acc.w += v.w;
        }
        float inv = sinv[q];
        acc.x *= inv; acc.y *= inv; acc.z *= inv; acc.w *= inv;
        ((float4*)(g_ctx + (bh*UU + q)*DD))[dv] = acc;
    }
}

// ---------------- K4 (half-range; launched twice) ----------------
__global__ __launch_bounds__(256) void k4_csum(const float* __restrict__ Vg, int c_off)
{
    __shared__ float sp[16][64];
    int c = blockIdx.x + c_off, bh = blockIdx.y, b = bh >> 3, h = bh & 7;
    int qd = threadIdx.x & 15, rg = threadIdx.x >> 4;
    int l0 = c * CLEN;
    float4 acc = make_float4(0.f, 0.f, 0.f, 0.f);
    #pragma unroll
    for (int t = 0; t < 4; t++) {
        int l = l0 + rg + t*16;
        float4 v = ((const float4*)(Vg + (((size_t)b*LL + l)*HH + h)*DD))[qd];
        acc.x += v.x; acc.y += v.y; acc.z += v.z; acc.w += v.w;
    }
    *(float4*)&sp[rg][qd*4] = acc;
    __syncthreads();
    if (threadIdx.x < 64) {
        int d = threadIdx.x;
        float s = 0.f;
        #pragma unroll
        for (int r = 0; r < 16; r++) s += sp[r][d];
        g_csum[(bh*NC + c)*DD + d] = s;
    }
}

// ---------------- K5 ----------------
__global__ __launch_bounds__(256) void k5_scan(const float* __restrict__ Vg,
                                               float* __restrict__ out)
{
    __shared__ int srank[1024];
    int bh = blockIdx.y, b = bh >> 3, h = bh & 7;
    int qd = threadIdx.x & 15, cl = threadIdx.x >> 4;
    int c = blockIdx.x * 16 + cl;
    int base_l = blockIdx.x * 1024;

    for (int i = threadIdx.x; i < 1024; i += 256)
        srank[i] = g_rank[bh*LL + base_l + i];
    __syncthreads();

    float4 acc = make_float4(0.f, 0.f, 0.f, 0.f);
    for (int cc = 0; cc < c; cc++) {
        float4 v = ((const float4*)(g_csum + (bh*NC + cc)*DD))[qd];
        acc.x += v.x; acc.y += v.y; acc.z += v.z; acc.w += v.w;
    }

    int l0 = c * CLEN;
    #pragma unroll 4
    for (int j = 0; j < CLEN; j++) {
        int l = l0 + j;
        float4 v = ((const float4*)(Vg + (((size_t)b*LL + l)*HH + h)*DD))[qd];
        acc.x += v.x; acc.y += v.y; acc.z += v.z; acc.w += v.w;
        float4 o = acc;
        int r = srank[l - base_l];
        if (r >= 0)
            o = ((const float4*)(g_ctx + (bh*UU + r)*DD))[qd];
        ((float4*)(out + (((size_t)b*LL + l)*HH + h)*DD))[qd] = o;
    }
}

extern "C" void kernel_launch(void* const* d_in, const int* in_sizes, int n_in,
                              void* d_out, int out_size)
{
    const float* Q    = (const float*)d_in[0];
    const float* K    = (const float*)d_in[1];
    const float* V    = (const float*)d_in[2];
    const int*   idxk = (const int*)d_in[3];
    int S = in_sizes[3];
    float* out = (float*)d_out;

    cudaFuncSetAttribute(k3_attn, cudaFuncAttributeMaxDynamicSharedMemorySize, K3_SMEM_BYTES);
    cudaFuncSetAttribute(k1_M,    cudaFuncAttributeMaxDynamicSharedMemorySize, K1_SMEM_BYTES);

    // k1_M stays at launch index 3 (ncu capture slot) to verify its speedup.
    k4_csum<<<dim3(NC/2, BH), 256>>>(V, 0);
    k4_csum<<<dim3(NC/2, BH), 256>>>(V, NC/2);
    k0_rinit<<<128, 256>>>();
    k1_M   <<<dim3(LL/QT, BH), 256, K1_SMEM_BYTES>>>(Q, K, idxk, S);
    k2_topk<<<BH, 256>>>();
    k3_attn<<<dim3(BH, NSPLIT), 256, K3_SMEM_BYTES>>>(K, V, Q);
    k3c_combine<<<BH, 256>>>();
    k5_scan<<<dim3(NC/16, BH), 256>>>(V, out);
}

// round 15
// speedup vs baseline: 1.3353x; 1.3353x over previous
#include <cuda_runtime.h>
#include <math_constants.h>

#define BB 16
#define LL 4096
#define HH 8
#define DD 64
#define BH (BB*HH)     // 128
#define UU 45
#define NC 64
#define CLEN 64        // LL/NC

#define TQ 64          // k3: queries padded to 64 for m16 MMA slabs
#define TK 32          // k3: key tile
#define SP 68          // padded smem row stride (64 floats + 4; 16B-aligned rows)
#define SPS 36         // padded stride for the 64x32 score tile
#define NSPLIT 8
#define KS (LL/NSPLIT) // 512 keys per split

#define QT 64          // k1: query tile rows
#define NT 4           // k1: tiles per block (256 queries/block)
#define SN 48          // k1: padded sample count (45 real + 3 zero)

// k3 dynamic smem (floats): sQ[TQ*SP], sS[TQ*SPS], sK[2][TK*SP], sV[2][TK*SP]
#define K3_SMEM_FLOATS (TQ*SP + TQ*SPS + 4*TK*SP)
#define K3_SMEM_BYTES  (K3_SMEM_FLOATS*4)
// k1 dynamic smem (floats): sQf[2][QT*SP] fp32 double-buffer; sKh,sKl [SN*SP]
#define K1_SMEM_FLOATS ((2*QT + 2*SN)*SP)
#define K1_SMEM_BYTES  (K1_SMEM_FLOATS*4)

typedef unsigned long long u64;
typedef unsigned int u32;

__device__ __forceinline__ void fma2(u64 &d, u64 a, u64 b){
    asm("fma.rn.f32x2 %0, %1, %2, %0;" : "+l"(d) : "l"(a), "l"(b));
}
__device__ __forceinline__ u64 pack2(float x, float y){
    u64 r; asm("mov.b64 %0, {%1, %2};" : "=l"(r) : "f"(x), "f"(y)); return r;
}
__device__ __forceinline__ float2 unpack2(u64 v){
    float2 r; asm("mov.b64 {%0, %1}, %2;" : "=f"(r.x), "=f"(r.y) : "l"(v)); return r;
}
__device__ __forceinline__ void cpa16(unsigned sdst, const void* gsrc){
    asm volatile("cp.async.cg.shared.global [%0], [%1], 16;" :: "r"(sdst), "l"(gsrc));
}
__device__ __forceinline__ void cpa_commit(){
    asm volatile("cp.async.commit_group;");
}
__device__ __forceinline__ u32 f2tf32(float x){
    u32 r; asm("cvt.rna.tf32.f32 %0, %1;" : "=r"(r) : "f"(x)); return r;
}
// m16n8k8 tf32 MMA, D += A*B, accumulate in place
__device__ __forceinline__ void mma_tf32(float4 &d, u32 a0, u32 a1, u32 a2, u32 a3,
                                         u32 b0, u32 b1){
    asm volatile(
        "mma.sync.aligned.m16n8k8.row.col.f32.tf32.tf32.f32 "
        "{%0,%1,%2,%3}, {%4,%5,%6,%7}, {%8,%9}, {%0,%1,%2,%3};"
        : "+f"(d.x), "+f"(d.y), "+f"(d.z), "+f"(d.w)
        : "r"(a0), "r"(a1), "r"(a2), "r"(a3), "r"(b0), "r"(b1));
}

// static scratch (no allocs allowed)
__device__ float g_M[BH*LL];
__device__ int   g_Mtop[BH*UU];
__device__ int   g_rank[BH*LL];
__device__ float g_ctx[BH*UU*DD];
__device__ float g_csum[BH*NC*DD];
__device__ float g_pl[BH*NSPLIT*TQ];
__device__ float g_po[(size_t)BH*NSPLIT*TQ*DD];

// ---------------- K0: init g_rank to -1 ----------------
__global__ __launch_bounds__(256) void k0_rinit()
{
    int4 m1 = make_int4(-1,-1,-1,-1);
    int idx = blockIdx.x * 256 + threadIdx.x;
    #pragma unroll
    for (int t = 0; t < 4; t++)
        ((int4*)g_rank)[idx + t*32768] = m1;
}

// ---------------- K1 v3: M scores via 3xTF32 MMA, 4 Q-tiles/block, cp.async pipeline ----------------
__global__ __launch_bounds__(256) void k1_M(const float* __restrict__ Q,
                                            const float* __restrict__ K,
                                            const int* __restrict__ idxk, int S)
{
    extern __shared__ __align__(16) float dyn[];
    float* sQf = dyn;                 // 2 x QT*SP fp32 (double buffer)
    float* sKh = dyn + 2*QT*SP;       // SN*SP
    float* sKl = sKh + SN*SP;         // SN*SP

    __shared__ float pmax[QT][2];
    __shared__ float psum[QT][2];

    int bh = blockIdx.y;
    int b = bh >> 3, h = bh & 7;
    int q0 = blockIdx.x * (QT*NT);
    int tid = threadIdx.x;

    // cp.async Q-tile loader role
    int lr = tid >> 4, ldv = tid & 15;
    unsigned sQ_s = (unsigned)__cvta_generic_to_shared(sQf);
    size_t qcol = ((size_t)b*LL)*HH*DD + (size_t)h*DD + ldv*4;

    // issue tile 0 into buffer 0 (overlaps K2 build below)
    #pragma unroll
    for (int t = 0; t < 4; t++) {
        int r = lr + 16*t;
        cpa16(sQ_s + (unsigned)((r*SP + ldv*4)*4),
              Q + qcol + (size_t)(q0 + r)*HH*DD);
    }
    cpa_commit();

    // build K2 tile (squared sampled K rows), split hi/lo tf32 — once per block
    for (int i = tid; i < SN*DD; i += 256) {
        int s = i >> 6, d = i & 63;
        float v = 0.f;
        if (s < S) {
            int kk = idxk[s];
            v = K[(((size_t)b*LL + kk)*HH + h)*DD + d];
        }
        float sq = v * v;
        float hi = __uint_as_float(f2tf32(sq));
        float lo = __uint_as_float(f2tf32(sq - hi));
        sKh[s*SP + d] = hi;
        sKl[s*SP + d] = lo;
    }

    // MMA warp roles (identical fragment mapping to the verified R14 kernel)
    int wid = tid >> 5, lane = tid & 31;
    int slab = wid >> 1, nhalf = wid & 1;   // 4 M-slabs x 2 N-halves
    int g = lane >> 2, tig = lane & 3;
    int rowA = slab*16 + g, rowB = rowA + 8;

    const u32* Kh = (const u32*)sKh;
    const u32* Kl = (const u32*)sKl;

    for (int tile = 0; tile < NT; tile++) {
        // issue next tile into the other buffer, then wait for current
        if (tile < NT-1) {
            unsigned dstb = sQ_s + (unsigned)((((tile+1)&1)*QT*SP)*4);
            int qt = q0 + (tile+1)*QT;
            #pragma unroll
            for (int t = 0; t < 4; t++) {
                int r = lr + 16*t;
                cpa16(dstb + (unsigned)((r*SP + ldv*4)*4),
                      Q + qcol + (size_t)(qt + r)*HH*DD);
            }
            cpa_commit();
            asm volatile("cp.async.wait_group 1;");
        } else {
            asm volatile("cp.async.wait_group 0;");
        }
        __syncthreads();   // current Q buffer (and on tile 0: K2, pmax free) ready

        const float* sQt = sQf + (tile&1)*QT*SP;

        float4 dacc[3];
        #pragma unroll
        for (int nt = 0; nt < 3; nt++) dacc[nt] = make_float4(0.f,0.f,0.f,0.f);

        #pragma unroll
        for (int st = 0; st < 8; st++) {
            int ko = st*8;
            // A fragments: fp32 from smem, hi = mask-truncate to tf32, lo = residual
            float af0 = sQt[rowA*SP + tig + ko];
            float af1 = sQt[rowB*SP + tig + ko];
            float af2 = sQt[rowA*SP + tig + 4 + ko];
            float af3 = sQt[rowB*SP + tig + 4 + ko];
            u32 ah0 = __float_as_uint(af0) & 0xFFFFE000u;
            u32 ah1 = __float_as_uint(af1) & 0xFFFFE000u;
            u32 ah2 = __float_as_uint(af2) & 0xFFFFE000u;
            u32 ah3 = __float_as_uint(af3) & 0xFFFFE000u;
            u32 al0 = __float_as_uint(af0 - __uint_as_float(ah0));
            u32 al1 = __float_as_uint(af1 - __uint_as_float(ah1));
            u32 al2 = __float_as_uint(af2 - __uint_as_float(ah2));
            u32 al3 = __float_as_uint(af3 - __uint_as_float(ah3));
            #pragma unroll
            for (int nt = 0; nt < 3; nt++) {
                int nrow = nhalf*24 + nt*8 + g;
                int kb = nrow*SP + ko;
                u32 bh0 = Kh[kb + tig], bh1 = Kh[kb + tig + 4];
                u32 bl0 = Kl[kb + tig], bl1 = Kl[kb + tig + 4];
                mma_tf32(dacc[nt], ah0, ah1, ah2, ah3, bh0, bh1);
                mma_tf32(dacc[nt], ah0, ah1, ah2, ah3, bl0, bl1);
                mma_tf32(dacc[nt], al0, al1, al2, al3, bh0, bh1);
            }
        }

        // per-row max (pad cols masked) and sum (pad cols exact 0)
        float mxA = -CUDART_INF_F, mxB = -CUDART_INF_F;
        float smA = 0.f, smB = 0.f;
        #pragma unroll
        for (int nt = 0; nt < 3; nt++) {
            int c0 = nhalf*24 + nt*8 + 2*tig;
            float4 d = dacc[nt];
            if (c0 < UU)     { mxA = fmaxf(mxA, d.x); mxB = fmaxf(mxB, d.z); }
            if (c0 + 1 < UU) { mxA = fmaxf(mxA, d.y); mxB = fmaxf(mxB, d.w); }
            smA += d.x + d.y;
            smB += d.z + d.w;
        }
        #pragma unroll
        for (int o = 1; o <= 2; o <<= 1) {
            mxA = fmaxf(mxA, __shfl_xor_sync(0xffffffffu, mxA, o));
            mxB = fmaxf(mxB, __shfl_xor_sync(0xffffffffu, mxB, o));
            smA += __shfl_xor_sync(0xffffffffu, smA, o);
            smB += __shfl_xor_sync(0xffffffffu, smB, o);
        }
        if (tig == 0) {
            pmax[slab*16 + g][nhalf] = mxA;      psum[slab*16 + g][nhalf] = smA;
            pmax[slab*16 + g + 8][nhalf] = mxB;  psum[slab*16 + g + 8][nhalf] = smB;
        }
        __syncthreads();
        if (tid < QT) {
            float mx = fmaxf(pmax[tid][0], pmax[tid][1]);
            float sm = psum[tid][0] + psum[tid][1];
            g_M[bh*LL + q0 + tile*QT + tid] = mx - sm * (1.0f / (float)LL);
        }
        // pmax/psum reuse is protected by the wait+__syncthreads at the top of
        // the next iteration (writes there happen-after these reads block-wide).
    }
}

// ---------------- K2 ----------------
__global__ __launch_bounds__(256) void k2_topk()
{
    __shared__ float sM[LL];
    __shared__ float rv[8];
    __shared__ int   ri[8];
    int bh = blockIdx.x;
    for (int i = threadIdx.x; i < LL/4; i += 256)
        ((float4*)sM)[i] = ((const float4*)(g_M + bh*LL))[i];
    __syncthreads();

    int lane = threadIdx.x & 31, wid = threadIdx.x >> 5;
    for (int it = 0; it < UU; it++) {
        float bv = -CUDART_INF_F; int bi = 0x7fffffff;
        for (int i = threadIdx.x; i < LL; i += 256) {
            float v = sM[i];
            if (v > bv || (v == bv && i < bi)) { bv = v; bi = i; }
        }
        #pragma unroll
        for (int o = 16; o > 0; o >>= 1) {
            float ov = __shfl_down_sync(0xffffffffu, bv, o);
            int   oi = __shfl_down_sync(0xffffffffu, bi, o);
            if (ov > bv || (ov == bv && oi < bi)) { bv = ov; bi = oi; }
        }
        if (lane == 0) { rv[wid] = bv; ri[wid] = bi; }
        __syncthreads();
        if (threadIdx.x == 0) {
            for (int w = 1; w < 8; w++)
                if (rv[w] > bv || (rv[w] == bv && ri[w] < bi)) { bv = rv[w]; bi = ri[w]; }
            g_Mtop[bh*UU + it] = bi;
            g_rank[bh*LL + bi] = it;
            sM[bi] = -CUDART_INF_F;
        }
        __syncthreads();
    }
}

// ---------------- K3: split-K flash; QK via tf32 MMA; m=0 softmax ----------------
__global__ __launch_bounds__(256, 3) void k3_attn(const float* __restrict__ Kg,
                                                  const float* __restrict__ Vg,
                                                  const float* __restrict__ Qg)
{
    extern __shared__ __align__(16) float dyn[];
    float* sQ = dyn;                          // TQ*SP
    float* sS = dyn + TQ*SP;                  // TQ*SPS
    float* sK = dyn + TQ*SP + TQ*SPS;         // 2 x TK*SP
    float* sV = sK + 2*TK*SP;                 // 2 x TK*SP

    __shared__ int   s_qi0[TQ];
    __shared__ int   s_qi[TQ];                // sorted DESCENDING
    __shared__ int   s_ou[TQ];
    __shared__ float sLp[TQ*2];               // per-row l partials (2 N-halves)

    int split = blockIdx.y;
    int bh = blockIdx.x;
    int b = bh >> 3, h = bh & 7;
    int tid = threadIdx.x;
    int ks = split * KS;

    if (tid < TQ) s_qi0[tid] = (tid < UU) ? g_Mtop[bh*UU + tid] : -1;
    __syncthreads();
    if (tid < TQ) {
        int qi = s_qi0[tid];
        int r = 0;
        #pragma unroll
        for (int j = 0; j < TQ; j++) {
            int qj = s_qi0[j];
            r += (qj > qi) || (qj == qi && j < tid);   // descending
        }
        s_qi[r] = qi;
        s_ou[r] = tid;
    }
    __syncthreads();
    int maxq = s_qi[0];

    for (int i = tid; i < TQ*16; i += 256) {
        int q = i >> 4, dv = i & 15;
        int row = s_qi[q];
        float4 v = make_float4(0.f, 0.f, 0.f, 0.f);
        if (row >= 0)
            v = ((const float4*)(Qg + (((size_t)b*LL + row)*HH + h)*DD))[dv];
        ((float4*)(sQ + q*SP))[dv] = v;
    }

    // QK MMA warp roles
    int wid2 = tid >> 5, lane = tid & 31;
    int slab = wid2 >> 1;
    int nhalf = wid2 & 1;
    int g = lane >> 2, tig = lane & 3;
    int rowA = slab*16 + g, rowB = rowA + 8;
    int wrow = slab*16 - (slab*16) % 3;

    // PV roles
    int qg = tid >> 4, lg = tid & 15;
    int q0 = qg*3, d0g = lg;

    __syncthreads();
    int qiA = s_qi[rowA], qiB = s_qi[rowB];
    int wqi = s_qi[wrow];
    int pvq = s_qi[q0];

    float l_r[3] = {0.f, 0.f, 0.f};
    u64 o0[3] = {0ull,0ull,0ull}, o1[3] = {0ull,0ull,0ull};

    const float scale = 0.125f;
    int tend = min(ks + KS, maxq + 1);

    int lr = tid >> 4, ldv = tid & 15;
    unsigned sK_s = (unsigned)__cvta_generic_to_shared(sK);
    unsigned sV_s = (unsigned)__cvta_generic_to_shared(sV);
    size_t grow = ((size_t)b*LL)*HH*DD + (size_t)h*DD + ldv*4;

    if (ks < tend) {
        #pragma unroll
        for (int t = 0; t < 2; t++) {
            int r = lr + 16*t;
            size_t go = grow + (size_t)(ks + r)*HH*DD;
            unsigned so = (unsigned)((r*SP + ldv*4)*4);
            cpa16(sK_s + so, Kg + go);
            cpa16(sV_s + so, Vg + go);
        }
        cpa_commit();
    }
    __syncthreads();

    int buf = 0;
    for (int t0 = ks; t0 < tend; t0 += TK, buf ^= 1) {
        int tn = t0 + TK;
        bool more = (tn < tend);

        if (more) {
            unsigned kb = sK_s + (buf^1)*TK*SP*4;
            unsigned vb = sV_s + (buf^1)*TK*SP*4;
            #pragma unroll
            for (int t = 0; t < 2; t++) {
                int r = lr + 16*t;
                size_t go = grow + (size_t)(tn + r)*HH*DD;
                unsigned so = (unsigned)((r*SP + ldv*4)*4);
                cpa16(kb + so, Kg + go);
                cpa16(vb + so, Vg + go);
            }
            cpa_commit();
            asm volatile("cp.async.wait_group 1;");
        } else {
            asm volatile("cp.async.wait_group 0;");
        }
        __syncthreads();

        const float* cK = sK + buf*TK*SP;
        const float* cV = sV + buf*TK*SP;

        // QK via tf32 MMA
        if (wqi >= t0) {
            const u32* sQu = (const u32*)sQ;
            const u32* cKu = (const u32*)cK;
            float4 d0 = make_float4(0.f,0.f,0.f,0.f);
            float4 d1 = make_float4(0.f,0.f,0.f,0.f);
            #pragma unroll
            for (int st = 0; st < 8; st++) {
                int ko = st*8;
                u32 a0 = sQu[rowA*SP + tig + ko];
                u32 a1 = sQu[rowB*SP + tig + ko];
                u32 a2 = sQu[rowA*SP + tig + 4 + ko];
                u32 a3 = sQu[rowB*SP + tig + 4 + ko];
                int kn0 = (nhalf*16 + g)*SP + tig + ko;
                int kn1 = (nhalf*16 + 8 + g)*SP + tig + ko;
                u32 b00 = cKu[kn0],     b01 = cKu[kn0 + 4];
                u32 b10 = cKu[kn1],     b11 = cKu[kn1 + 4];
                mma_tf32(d0, a0, a1, a2, a3, b00, b01);
                mma_tf32(d1, a0, a1, a2, a3, b10, b11);
            }
            float rsumA = 0.f, rsumB = 0.f;
            #pragma unroll
            for (int nt = 0; nt < 2; nt++) {
                float4 d = nt ? d1 : d0;
                int c0 = nhalf*16 + nt*8 + 2*tig;
                int k0g = t0 + c0;
                float pA0 = (k0g   <= qiA) ? __expf(d.x * scale) : 0.f;
                float pA1 = (k0g+1 <= qiA) ? __expf(d.y * scale) : 0.f;
                float pB0 = (k0g   <= qiB) ? __expf(d.z * scale) : 0.f;
                float pB1 = (k0g+1 <= qiB) ? __expf(d.w * scale) : 0.f;
                *(float2*)(sS + rowA*SPS + c0) = make_float2(pA0, pA1);
                *(float2*)(sS + rowB*SPS + c0) = make_float2(pB0, pB1);
                rsumA += pA0 + pA1;
                rsumB += pB0 + pB1;
            }
            rsumA += __shfl_xor_sync(0xffffffffu, rsumA, 1);
            rsumA += __shfl_xor_sync(0xffffffffu, rsumA, 2);
            rsumB += __shfl_xor_sync(0xffffffffu, rsumB, 1);
            rsumB += __shfl_xor_sync(0xffffffffu, rsumB, 2);
            if (tig == 0) {
                sLp[rowA*2 + nhalf] = rsumA;
                sLp[rowB*2 + nhalf] = rsumB;
            }
        }
        __syncthreads();

        // PV (scalar packed FMA)
        if (pvq >= t0) {
            if (lg == 0) {
                #pragma unroll
                for (int j = 0; j < 3; j++)
                    l_r[j] += sLp[(q0+j)*2] + sLp[(q0+j)*2 + 1];
            }
            for (int kb2 = 0; kb2 < TK; kb2 += 4) {
                float4 sv[3];
                #pragma unroll
                for (int j = 0; j < 3; j++)
                    sv[j] = *(const float4*)(sS + (q0+j)*SPS + kb2);
                ulonglong2 vv[4];
                #pragma unroll
                for (int t = 0; t < 4; t++)
                    vv[t] = ((const ulonglong2*)(cV + (kb2+t)*SP))[d0g];
                #pragma unroll
                for (int j = 0; j < 3; j++) {
                    float sj[4] = {sv[j].x, sv[j].y, sv[j].z, sv[j].w};
                    #pragma unroll
                    for (int t = 0; t < 4; t++) {
                        u64 sp = pack2(sj[t], sj[t]);
                        fma2(o0[j], sp, vv[t].x);
                        fma2(o1[j], sp, vv[t].y);
                    }
                }
            }
        }
        __syncthreads();
    }

    // write partials
    int pbase = (bh*NSPLIT + split)*TQ;
    #pragma unroll
    for (int j = 0; j < 3; j++) {
        int q = q0 + j;
        int ou = s_ou[q];
        if (ou < UU) {
            float2 a = unpack2(o0[j]);
            float2 c = unpack2(o1[j]);
            ((float4*)(g_po + ((size_t)(pbase + ou))*DD))[d0g] =
                make_float4(a.x, a.y, c.x, c.y);
            if (lg == 0)
                g_pl[pbase + ou] = l_r[j];
        }
    }
}

// ---------------- K3c: combine split partials (m=0: plain sums) ----------------
__global__ __launch_bounds__(256) void k3c_combine()
{
    __shared__ float sinv[UU];
    int bh = blockIdx.x;
    int tid = threadIdx.x;
    if (tid < UU) {
        float l = 0.f;
        #pragma unroll
        for (int s = 0; s < NSPLIT; s++)
            l += g_pl[(bh*NSPLIT + s)*TQ + tid];
        sinv[tid] = 1.f / l;
    }
    __syncthreads();
    for (int idx = tid; idx < UU*16; idx += 256) {
        int q = idx >> 4, dv = idx & 15;
        float4 acc = make_float4(0.f, 0.f, 0.f, 0.f);
        #pragma unroll
        for (int s = 0; s < NSPLIT; s++) {
            float4 v = ((const float4*)(g_po + ((size_t)((bh*NSPLIT + s)*TQ + q))*DD))[dv];
            acc.x += v.x; acc.y += v.y; acc.z += v.z; acc.w += v.w;
        }
        float inv = sinv[q];
        acc.x *= inv; acc.y *= inv; acc.z *= inv; acc.w *= inv;
        ((float4*)(g_ctx + (bh*UU + q)*DD))[dv] = acc;
    }
}

// ---------------- K4 (half-range; launched twice) ----------------
__global__ __launch_bounds__(256) void k4_csum(const float* __restrict__ Vg, int c_off)
{
    __shared__ float sp[16][64];
    int c = blockIdx.x + c_off, bh = blockIdx.y, b = bh >> 3, h = bh & 7;
    int qd = threadIdx.x & 15, rg = threadIdx.x >> 4;
    int l0 = c * CLEN;
    float4 acc = make_float4(0.f, 0.f, 0.f, 0.f);
    #pragma unroll
    for (int t = 0; t < 4; t++) {
        int l = l0 + rg + t*16;
        float4 v = ((const float4*)(Vg + (((size_t)b*LL + l)*HH + h)*DD))[qd];
        acc.x += v.x; acc.y += v.y; acc.z += v.z; acc.w += v.w;
    }
    *(float4*)&sp[rg][qd*4] = acc;
    __syncthreads();
    if (threadIdx.x < 64) {
        int d = threadIdx.x;
        float s = 0.f;
        #pragma unroll
        for (int r = 0; r < 16; r++) s += sp[r][d];
        g_csum[(bh*NC + c)*DD + d] = s;
    }
}

// ---------------- K5 ----------------
__global__ __launch_bounds__(256) void k5_scan(const float* __restrict__ Vg,
                                               float* __restrict__ out)
{
    __shared__ int srank[1024];
    int bh = blockIdx.y, b = bh >> 3, h = bh & 7;
    int qd = threadIdx.x & 15, cl = threadIdx.x >> 4;
    int c = blockIdx.x * 16 + cl;
    int base_l = blockIdx.x * 1024;

    for (int i = threadIdx.x; i < 1024; i += 256)
        srank[i] = g_rank[bh*LL + base_l + i];
    __syncthreads();

    float4 acc = make_float4(0.f, 0.f, 0.f, 0.f);
    for (int cc = 0; cc < c; cc++) {
        float4 v = ((const float4*)(g_csum + (bh*NC + cc)*DD))[qd];
        acc.x += v.x; acc.y += v.y; acc.z += v.z; acc.w += v.w;
    }

    int l0 = c * CLEN;
    #pragma unroll 4
    for (int j = 0; j < CLEN; j++) {
        int l = l0 + j;
        float4 v = ((const float4*)(Vg + (((size_t)b*LL + l)*HH + h)*DD))[qd];
        acc.x += v.x; acc.y += v.y; acc.z += v.z; acc.w += v.w;
        float4 o = acc;
        int r = srank[l - base_l];
        if (r >= 0)
            o = ((const float4*)(g_ctx + (bh*UU + r)*DD))[qd];
        ((float4*)(out + (((size_t)b*LL + l)*HH + h)*DD))[qd] = o;
    }
}

extern "C" void kernel_launch(void* const* d_in, const int* in_sizes, int n_in,
                              void* d_out, int out_size)
{
    const float* Q    = (const float*)d_in[0];
    const float* K    = (const float*)d_in[1];
    const float* V    = (const float*)d_in[2];
    const int*   idxk = (const int*)d_in[3];
    int S = in_sizes[3];
    float* out = (float*)d_out;

    cudaFuncSetAttribute(k3_attn, cudaFuncAttributeMaxDynamicSharedMemorySize, K3_SMEM_BYTES);
    cudaFuncSetAttribute(k1_M,    cudaFuncAttributeMaxDynamicSharedMemorySize, K1_SMEM_BYTES);

    // k1_M stays at launch index 3 (ncu capture slot) to verify the restructure.
    k4_csum<<<dim3(NC/2, BH), 256>>>(V, 0);
    k4_csum<<<dim3(NC/2, BH), 256>>>(V, NC/2);
    k0_rinit<<<128, 256>>>();
    k1_M   <<<dim3(LL/(QT*NT), BH), 256, K1_SMEM_BYTES>>>(Q, K, idxk, S);
    k2_topk<<<BH, 256>>>();
    k3_attn<<<dim3(BH, NSPLIT), 256, K3_SMEM_BYTES>>>(K, V, Q);
    k3c_combine<<<BH, 256>>>();
    k5_scan<<<dim3(NC/16, BH), 256>>>(V, out);
}

// round 16
// speedup vs baseline: 1.5199x; 1.1383x over previous
#include <cuda_runtime.h>
#include <math_constants.h>

#define BB 16
#define LL 4096
#define HH 8
#define DD 64
#define BH (BB*HH)     // 128
#define UU 45
#define NC 64
#define CLEN 64        // LL/NC

#define TQ 64          // k3: queries padded to 64 for m16 MMA slabs
#define TK 32          // k3: key tile
#define SP 68          // padded smem row stride for Q/K rows (conflict-free for QK frags)
#define SPV 72         // padded stride for V rows (72%32=8 -> conflict-free PV B frags)
#define SPS 36         // padded stride for the 64x32 score tile
#define NSPLIT 8
#define KS (LL/NSPLIT) // 512 keys per split

#define QT 64          // k1: query tile rows
#define NT 4           // k1: tiles per block (256 queries/block)
#define SN 48          // k1: padded sample count (45 real + 3 zero)

// k3 dynamic smem (floats): sQ[TQ*SP], sS[TQ*SPS], sK[2][TK*SP], sV[2][TK*SPV]
#define K3_SMEM_FLOATS (TQ*SP + TQ*SPS + 2*TK*SP + 2*TK*SPV)
#define K3_SMEM_BYTES  (K3_SMEM_FLOATS*4)
// k1 dynamic smem (floats): sQf[2][QT*SP] fp32 double-buffer; sKh,sKl [SN*SP]
#define K1_SMEM_FLOATS ((2*QT + 2*SN)*SP)
#define K1_SMEM_BYTES  (K1_SMEM_FLOATS*4)

typedef unsigned long long u64;
typedef unsigned int u32;

__device__ __forceinline__ void fma2(u64 &d, u64 a, u64 b){
    asm("fma.rn.f32x2 %0, %1, %2, %0;" : "+l"(d) : "l"(a), "l"(b));
}
__device__ __forceinline__ u64 pack2(float x, float y){
    u64 r; asm("mov.b64 %0, {%1, %2};" : "=l"(r) : "f"(x), "f"(y)); return r;
}
__device__ __forceinline__ float2 unpack2(u64 v){
    float2 r; asm("mov.b64 {%0, %1}, %2;" : "=f"(r.x), "=f"(r.y) : "l"(v)); return r;
}
__device__ __forceinline__ void cpa16(unsigned sdst, const void* gsrc){
    asm volatile("cp.async.cg.shared.global [%0], [%1], 16;" :: "r"(sdst), "l"(gsrc));
}
__device__ __forceinline__ void cpa_commit(){
    asm volatile("cp.async.commit_group;");
}
__device__ __forceinline__ u32 f2tf32(float x){
    u32 r; asm("cvt.rna.tf32.f32 %0, %1;" : "=r"(r) : "f"(x)); return r;
}
// m16n8k8 tf32 MMA, D += A*B, accumulate in place
__device__ __forceinline__ void mma_tf32(float4 &d, u32 a0, u32 a1, u32 a2, u32 a3,
                                         u32 b0, u32 b1){
    asm volatile(
        "mma.sync.aligned.m16n8k8.row.col.f32.tf32.tf32.f32 "
        "{%0,%1,%2,%3}, {%4,%5,%6,%7}, {%8,%9}, {%0,%1,%2,%3};"
        : "+f"(d.x), "+f"(d.y), "+f"(d.z), "+f"(d.w)
        : "r"(a0), "r"(a1), "r"(a2), "r"(a3), "r"(b0), "r"(b1));
}

// static scratch (no allocs allowed)
__device__ float g_M[BH*LL];
__device__ int   g_Mtop[BH*UU];
__device__ int   g_rank[BH*LL];
__device__ float g_ctx[BH*UU*DD];
__device__ float g_csum[BH*NC*DD];
__device__ float g_pl[BH*NSPLIT*TQ];
__device__ float g_po[(size_t)BH*NSPLIT*TQ*DD];

// ---------------- K0: init g_rank to -1 ----------------
__global__ __launch_bounds__(256) void k0_rinit()
{
    int4 m1 = make_int4(-1,-1,-1,-1);
    int idx = blockIdx.x * 256 + threadIdx.x;
    #pragma unroll
    for (int t = 0; t < 4; t++)
        ((int4*)g_rank)[idx + t*32768] = m1;
}

// ---------------- K1 v3: M scores via 3xTF32 MMA, 4 Q-tiles/block, cp.async pipeline ----------------
__global__ __launch_bounds__(256) void k1_M(const float* __restrict__ Q,
                                            const float* __restrict__ K,
                                            const int* __restrict__ idxk, int S)
{
    extern __shared__ __align__(16) float dyn[];
    float* sQf = dyn;                 // 2 x QT*SP fp32 (double buffer)
    float* sKh = dyn + 2*QT*SP;       // SN*SP
    float* sKl = sKh + SN*SP;         // SN*SP

    __shared__ float pmax[QT][2];
    __shared__ float psum[QT][2];

    int bh = blockIdx.y;
    int b = bh >> 3, h = bh & 7;
    int q0 = blockIdx.x * (QT*NT);
    int tid = threadIdx.x;

    int lr = tid >> 4, ldv = tid & 15;
    unsigned sQ_s = (unsigned)__cvta_generic_to_shared(sQf);
    size_t qcol = ((size_t)b*LL)*HH*DD + (size_t)h*DD + ldv*4;

    #pragma unroll
    for (int t = 0; t < 4; t++) {
        int r = lr + 16*t;
        cpa16(sQ_s + (unsigned)((r*SP + ldv*4)*4),
              Q + qcol + (size_t)(q0 + r)*HH*DD);
    }
    cpa_commit();

    for (int i = tid; i < SN*DD; i += 256) {
        int s = i >> 6, d = i & 63;
        float v = 0.f;
        if (s < S) {
            int kk = idxk[s];
            v = K[(((size_t)b*LL + kk)*HH + h)*DD + d];
        }
        float sq = v * v;
        float hi = __uint_as_float(f2tf32(sq));
        float lo = __uint_as_float(f2tf32(sq - hi));
        sKh[s*SP + d] = hi;
        sKl[s*SP + d] = lo;
    }

    int wid = tid >> 5, lane = tid & 31;
    int slab = wid >> 1, nhalf = wid & 1;
    int g = lane >> 2, tig = lane & 3;
    int rowA = slab*16 + g, rowB = rowA + 8;

    const u32* Kh = (const u32*)sKh;
    const u32* Kl = (const u32*)sKl;

    for (int tile = 0; tile < NT; tile++) {
        if (tile < NT-1) {
            unsigned dstb = sQ_s + (unsigned)((((tile+1)&1)*QT*SP)*4);
            int qt = q0 + (tile+1)*QT;
            #pragma unroll
            for (int t = 0; t < 4; t++) {
                int r = lr + 16*t;
                cpa16(dstb + (unsigned)((r*SP + ldv*4)*4),
                      Q + qcol + (size_t)(qt + r)*HH*DD);
            }
            cpa_commit();
            asm volatile("cp.async.wait_group 1;");
        } else {
            asm volatile("cp.async.wait_group 0;");
        }
        __syncthreads();

        const float* sQt = sQf + (tile&1)*QT*SP;

        float4 dacc[3];
        #pragma unroll
        for (int nt = 0; nt < 3; nt++) dacc[nt] = make_float4(0.f,0.f,0.f,0.f);

        #pragma unroll
        for (int st = 0; st < 8; st++) {
            int ko = st*8;
            float af0 = sQt[rowA*SP + tig + ko];
            float af1 = sQt[rowB*SP + tig + ko];
            float af2 = sQt[rowA*SP + tig + 4 + ko];
            float af3 = sQt[rowB*SP + tig + 4 + ko];
            u32 ah0 = __float_as_uint(af0) & 0xFFFFE000u;
            u32 ah1 = __float_as_uint(af1) & 0xFFFFE000u;
            u32 ah2 = __float_as_uint(af2) & 0xFFFFE000u;
            u32 ah3 = __float_as_uint(af3) & 0xFFFFE000u;
            u32 al0 = __float_as_uint(af0 - __uint_as_float(ah0));
            u32 al1 = __float_as_uint(af1 - __uint_as_float(ah1));
            u32 al2 = __float_as_uint(af2 - __uint_as_float(ah2));
            u32 al3 = __float_as_uint(af3 - __uint_as_float(ah3));
            #pragma unroll
            for (int nt = 0; nt < 3; nt++) {
                int nrow = nhalf*24 + nt*8 + g;
                int kb = nrow*SP + ko;
                u32 bh0 = Kh[kb + tig], bh1 = Kh[kb + tig + 4];
                u32 bl0 = Kl[kb + tig], bl1 = Kl[kb + tig + 4];
                mma_tf32(dacc[nt], ah0, ah1, ah2, ah3, bh0, bh1);
                mma_tf32(dacc[nt], ah0, ah1, ah2, ah3, bl0, bl1);
                mma_tf32(dacc[nt], al0, al1, al2, al3, bh0, bh1);
            }
        }

        float mxA = -CUDART_INF_F, mxB = -CUDART_INF_F;
        float smA = 0.f, smB = 0.f;
        #pragma unroll
        for (int nt = 0; nt < 3; nt++) {
            int c0 = nhalf*24 + nt*8 + 2*tig;
            float4 d = dacc[nt];
            if (c0 < UU)     { mxA = fmaxf(mxA, d.x); mxB = fmaxf(mxB, d.z); }
            if (c0 + 1 < UU) { mxA = fmaxf(mxA, d.y); mxB = fmaxf(mxB, d.w); }
            smA += d.x + d.y;
            smB += d.z + d.w;
        }
        #pragma unroll
        for (int o = 1; o <= 2; o <<= 1) {
            mxA = fmaxf(mxA, __shfl_xor_sync(0xffffffffu, mxA, o));
            mxB = fmaxf(mxB, __shfl_xor_sync(0xffffffffu, mxB, o));
            smA += __shfl_xor_sync(0xffffffffu, smA, o);
            smB += __shfl_xor_sync(0xffffffffu, smB, o);
        }
        if (tig == 0) {
            pmax[slab*16 + g][nhalf] = mxA;      psum[slab*16 + g][nhalf] = smA;
            pmax[slab*16 + g + 8][nhalf] = mxB;  psum[slab*16 + g + 8][nhalf] = smB;
        }
        __syncthreads();
        if (tid < QT) {
            float mx = fmaxf(pmax[tid][0], pmax[tid][1]);
            float sm = psum[tid][0] + psum[tid][1];
            g_M[bh*LL + q0 + tile*QT + tid] = mx - sm * (1.0f / (float)LL);
        }
    }
}

// ---------------- K2 ----------------
__global__ __launch_bounds__(256) void k2_topk()
{
    __shared__ float sM[LL];
    __shared__ float rv[8];
    __shared__ int   ri[8];
    int bh = blockIdx.x;
    for (int i = threadIdx.x; i < LL/4; i += 256)
        ((float4*)sM)[i] = ((const float4*)(g_M + bh*LL))[i];
    __syncthreads();

    int lane = threadIdx.x & 31, wid = threadIdx.x >> 5;
    for (int it = 0; it < UU; it++) {
        float bv = -CUDART_INF_F; int bi = 0x7fffffff;
        for (int i = threadIdx.x; i < LL; i += 256) {
            float v = sM[i];
            if (v > bv || (v == bv && i < bi)) { bv = v; bi = i; }
        }
        #pragma unroll
        for (int o = 16; o > 0; o >>= 1) {
            float ov = __shfl_down_sync(0xffffffffu, bv, o);
            int   oi = __shfl_down_sync(0xffffffffu, bi, o);
            if (ov > bv || (ov == bv && oi < bi)) { bv = ov; bi = oi; }
        }
        if (lane == 0) { rv[wid] = bv; ri[wid] = bi; }
        __syncthreads();
        if (threadIdx.x == 0) {
            for (int w = 1; w < 8; w++)
                if (rv[w] > bv || (rv[w] == bv && ri[w] < bi)) { bv = rv[w]; bi = ri[w]; }
            g_Mtop[bh*UU + it] = bi;
            g_rank[bh*LL + bi] = it;
            sM[bi] = -CUDART_INF_F;
        }
        __syncthreads();
    }
}

// ---------------- K3: split-K flash; QK AND PV via tf32 MMA; m=0 softmax ----------------
__global__ __launch_bounds__(256, 3) void k3_attn(const float* __restrict__ Kg,
                                                  const float* __restrict__ Vg,
                                                  const float* __restrict__ Qg)
{
    extern __shared__ __align__(16) float dyn[];
    float* sQ = dyn;                          // TQ*SP
    float* sS = dyn + TQ*SP;                  // TQ*SPS
    float* sK = dyn + TQ*SP + TQ*SPS;         // 2 x TK*SP
    float* sV = sK + 2*TK*SP;                 // 2 x TK*SPV

    __shared__ int   s_qi0[TQ];
    __shared__ int   s_qi[TQ];                // sorted DESCENDING
    __shared__ int   s_ou[TQ];
    __shared__ float sLp[TQ*2];               // per-row l partials (2 N-halves)

    int split = blockIdx.y;
    int bh = blockIdx.x;
    int b = bh >> 3, h = bh & 7;
    int tid = threadIdx.x;
    int ks = split * KS;

    if (tid < TQ) s_qi0[tid] = (tid < UU) ? g_Mtop[bh*UU + tid] : -1;
    __syncthreads();
    if (tid < TQ) {
        int qi = s_qi0[tid];
        int r = 0;
        #pragma unroll
        for (int j = 0; j < TQ; j++) {
            int qj = s_qi0[j];
            r += (qj > qi) || (qj == qi && j < tid);   // descending
        }
        s_qi[r] = qi;
        s_ou[r] = tid;
    }
    __syncthreads();
    int maxq = s_qi[0];

    for (int i = tid; i < TQ*16; i += 256) {
        int q = i >> 4, dv = i & 15;
        int row = s_qi[q];
        float4 v = make_float4(0.f, 0.f, 0.f, 0.f);
        if (row >= 0)
            v = ((const float4*)(Qg + (((size_t)b*LL + row)*HH + h)*DD))[dv];
        ((float4*)(sQ + q*SP))[dv] = v;
    }

    // MMA warp roles (shared by QK and PV)
    int wid2 = tid >> 5, lane = tid & 31;
    int slab = wid2 >> 1;                     // M slab (16 q rows)
    int nhalf = wid2 & 1;                     // QK: key half; PV: d half
    int g = lane >> 2, tig = lane & 3;
    int rowA = slab*16 + g, rowB = rowA + 8;

    __syncthreads();
    int qiA = s_qi[rowA], qiB = s_qi[rowB];
    int slab_qi = s_qi[slab*16];              // slab max (descending sort)
    int lgate_qi = (tid < TQ) ? s_qi[(tid>>4)<<4] : -1;

    float l_acc = 0.f;
    float4 oacc[4];
    #pragma unroll
    for (int nt = 0; nt < 4; nt++) oacc[nt] = make_float4(0.f,0.f,0.f,0.f);

    const float scale = 0.125f;
    int tend = min(ks + KS, maxq + 1);

    int lr = tid >> 4, ldv = tid & 15;
    unsigned sK_s = (unsigned)__cvta_generic_to_shared(sK);
    unsigned sV_s = (unsigned)__cvta_generic_to_shared(sV);
    size_t grow = ((size_t)b*LL)*HH*DD + (size_t)h*DD + ldv*4;

    if (ks < tend) {
        #pragma unroll
        for (int t = 0; t < 2; t++) {
            int r = lr + 16*t;
            size_t go = grow + (size_t)(ks + r)*HH*DD;
            cpa16(sK_s + (unsigned)((r*SP  + ldv*4)*4), Kg + go);
            cpa16(sV_s + (unsigned)((r*SPV + ldv*4)*4), Vg + go);
        }
        cpa_commit();
    }
    __syncthreads();

    int buf = 0;
    for (int t0 = ks; t0 < tend; t0 += TK, buf ^= 1) {
        int tn = t0 + TK;
        bool more = (tn < tend);

        if (more) {
            unsigned kb = sK_s + (unsigned)(((buf^1)*TK*SP)*4);
            unsigned vb = sV_s + (unsigned)(((buf^1)*TK*SPV)*4);
            #pragma unroll
            for (int t = 0; t < 2; t++) {
                int r = lr + 16*t;
                size_t go = grow + (size_t)(tn + r)*HH*DD;
                cpa16(kb + (unsigned)((r*SP  + ldv*4)*4), Kg + go);
                cpa16(vb + (unsigned)((r*SPV + ldv*4)*4), Vg + go);
            }
            cpa_commit();
            asm volatile("cp.async.wait_group 1;");
        } else {
            asm volatile("cp.async.wait_group 0;");
        }
        __syncthreads();

        const float* cK = sK + buf*TK*SP;
        const float* cV = sV + buf*TK*SPV;
        bool sact = (slab_qi >= t0);

        // ---------- QK via tf32 MMA ----------
        if (sact) {
            const u32* sQu = (const u32*)sQ;
            const u32* cKu = (const u32*)cK;
            float4 d0 = make_float4(0.f,0.f,0.f,0.f);
            float4 d1 = make_float4(0.f,0.f,0.f,0.f);
            #pragma unroll
            for (int st = 0; st < 8; st++) {
                int ko = st*8;
                u32 a0 = sQu[rowA*SP + tig + ko];
                u32 a1 = sQu[rowB*SP + tig + ko];
                u32 a2 = sQu[rowA*SP + tig + 4 + ko];
                u32 a3 = sQu[rowB*SP + tig + 4 + ko];
                int kn0 = (nhalf*16 + g)*SP + tig + ko;
                int kn1 = (nhalf*16 + 8 + g)*SP + tig + ko;
                u32 b00 = cKu[kn0],     b01 = cKu[kn0 + 4];
                u32 b10 = cKu[kn1],     b11 = cKu[kn1 + 4];
                mma_tf32(d0, a0, a1, a2, a3, b00, b01);
                mma_tf32(d1, a0, a1, a2, a3, b10, b11);
            }
            float rsumA = 0.f, rsumB = 0.f;
            #pragma unroll
            for (int nt = 0; nt < 2; nt++) {
                float4 d = nt ? d1 : d0;
                int c0 = nhalf*16 + nt*8 + 2*tig;
                int k0g = t0 + c0;
                float pA0 = (k0g   <= qiA) ? __expf(d.x * scale) : 0.f;
                float pA1 = (k0g+1 <= qiA) ? __expf(d.y * scale) : 0.f;
                float pB0 = (k0g   <= qiB) ? __expf(d.z * scale) : 0.f;
                float pB1 = (k0g+1 <= qiB) ? __expf(d.w * scale) : 0.f;
                *(float2*)(sS + rowA*SPS + c0) = make_float2(pA0, pA1);
                *(float2*)(sS + rowB*SPS + c0) = make_float2(pB0, pB1);
                rsumA += pA0 + pA1;
                rsumB += pB0 + pB1;
            }
            rsumA += __shfl_xor_sync(0xffffffffu, rsumA, 1);
            rsumA += __shfl_xor_sync(0xffffffffu, rsumA, 2);
            rsumB += __shfl_xor_sync(0xffffffffu, rsumB, 1);
            rsumB += __shfl_xor_sync(0xffffffffu, rsumB, 2);
            if (tig == 0) {
                sLp[rowA*2 + nhalf] = rsumA;
                sLp[rowB*2 + nhalf] = rsumB;
            }
        }
        __syncthreads();    // sS + sLp visible

        // ---------- l accumulation ----------
        if (tid < TQ && lgate_qi >= t0)
            l_acc += sLp[tid*2] + sLp[tid*2 + 1];

        // ---------- PV via tf32 MMA: O[16q x 32d] += P[16q x 32k] * V[32k x 32d] ----------
        if (sact) {
            const u32* sSu = (const u32*)sS;
            const u32* cVu = (const u32*)cV;
            #pragma unroll
            for (int ko = 0; ko < TK; ko += 8) {
                u32 a0 = sSu[rowA*SPS + tig + ko];
                u32 a1 = sSu[rowB*SPS + tig + ko];
                u32 a2 = sSu[rowA*SPS + tig + 4 + ko];
                u32 a3 = sSu[rowB*SPS + tig + 4 + ko];
                #pragma unroll
                for (int nt = 0; nt < 4; nt++) {
                    int dcol = nhalf*32 + nt*8 + g;
                    u32 b0 = cVu[(ko + tig)*SPV + dcol];
                    u32 b1 = cVu[(ko + tig + 4)*SPV + dcol];
                    mma_tf32(oacc[nt], a0, a1, a2, a3, b0, b1);
                }
            }
        }
        __syncthreads();    // all reads of this buffer + sS done before refill
    }

    // ---- write partials from MMA fragments ----
    int pbase = (bh*NSPLIT + split)*TQ;
    int ouA = s_ou[rowA], ouB = s_ou[rowB];
    #pragma unroll
    for (int nt = 0; nt < 4; nt++) {
        int d = nhalf*32 + nt*8 + 2*tig;
        if (ouA < UU)
            *(float2*)(g_po + (size_t)(pbase + ouA)*DD + d) = make_float2(oacc[nt].x, oacc[nt].y);
        if (ouB < UU)
            *(float2*)(g_po + (size_t)(pbase + ouB)*DD + d) = make_float2(oacc[nt].z, oacc[nt].w);
    }
    if (tid < TQ && s_ou[tid] < UU)
        g_pl[pbase + s_ou[tid]] = l_acc;
}

// ---------------- K3c: combine split partials (m=0: plain sums) ----------------
__global__ __launch_bounds__(256) void k3c_combine()
{
    __shared__ float sinv[UU];
    int bh = blockIdx.x;
    int tid = threadIdx.x;
    if (tid < UU) {
        float l = 0.f;
        #pragma unroll
        for (int s = 0; s < NSPLIT; s++)
            l += g_pl[(bh*NSPLIT + s)*TQ + tid];
        sinv[tid] = 1.f / l;
    }
    __syncthreads();
    for (int idx = tid; idx < UU*16; idx += 256) {
        int q = idx >> 4, dv = idx & 15;
        float4 acc = make_float4(0.f, 0.f, 0.f, 0.f);
        #pragma unroll
        for (int s = 0; s < NSPLIT; s++) {
            float4 v = ((const float4*)(g_po + ((size_t)((bh*NSPLIT + s)*TQ + q))*DD))[dv];
            acc.x += v.x; acc.y += v.y; acc.z += v.z; acc.w += v.w;
        }
        float inv = sinv[q];
        acc.x *= inv; acc.y *= inv; acc.z *= inv; acc.w *= inv;
        ((float4*)(g_ctx + (bh*UU + q)*DD))[dv] = acc;
    }
}

// ---------------- K4 (half-range; launched twice) ----------------
__global__ __launch_bounds__(256) void k4_csum(const float* __restrict__ Vg, int c_off)
{
    __shared__ float sp[16][64];
    int c = blockIdx.x + c_off, bh = blockIdx.y, b = bh >> 3, h = bh & 7;
    int qd = threadIdx.x & 15, rg = threadIdx.x >> 4;
    int l0 = c * CLEN;
    float4 acc = make_float4(0.f, 0.f, 0.f, 0.f);
    #pragma unroll
    for (int t = 0; t < 4; t++) {
        int l = l0 + rg + t*16;
        float4 v = ((const float4*)(Vg + (((size_t)b*LL + l)*HH + h)*DD))[qd];
        acc.x += v.x; acc.y += v.y; acc.z += v.z; acc.w += v.w;
    }
    *(float4*)&sp[rg][qd*4] = acc;
    __syncthreads();
    if (threadIdx.x < 64) {
        int d = threadIdx.x;
        float s = 0.f;
        #pragma unroll
        for (int r = 0; r < 16; r++) s += sp[r][d];
        g_csum[(bh*NC + c)*DD + d] = s;
    }
}

// ---------------- K5 ----------------
__global__ __launch_bounds__(256) void k5_scan(const float* __restrict__ Vg,
                                               float* __restrict__ out)
{
    __shared__ int srank[1024];
    int bh = blockIdx.y, b = bh >> 3, h = bh & 7;
    int qd = threadIdx.x & 15, cl = threadIdx.x >> 4;
    int c = blockIdx.x * 16 + cl;
    int base_l = blockIdx.x * 1024;

    for (int i = threadIdx.x; i < 1024; i += 256)
        srank[i] = g_rank[bh*LL + base_l + i];
    __syncthreads();

    float4 acc = make_float4(0.f, 0.f, 0.f, 0.f);
    for (int cc = 0; cc < c; cc++) {
        float4 v = ((const float4*)(g_csum + (bh*NC + cc)*DD))[qd];
        acc.x += v.x; acc.y += v.y; acc.z += v.z; acc.w += v.w;
    }

    int l0 = c * CLEN;
    #pragma unroll 4
    for (int j = 0; j < CLEN; j++) {
        int l = l0 + j;
        float4 v = ((const float4*)(Vg + (((size_t)b*LL + l)*HH + h)*DD))[qd];
        acc.x += v.x; acc.y += v.y; acc.z += v.z; acc.w += v.w;
        float4 o = acc;
        int r = srank[l - base_l];
        if (r >= 0)
            o = ((const float4*)(g_ctx + (bh*UU + r)*DD))[qd];
        ((float4*)(out + (((size_t)b*LL + l)*HH + h)*DD))[qd] = o;
    }
}

extern "C" void kernel_launch(void* const* d_in, const int* in_sizes, int n_in,
                              void* d_out, int out_size)
{
    const float* Q    = (const float*)d_in[0];
    const float* K    = (const float*)d_in[1];
    const float* V    = (const float*)d_in[2];
    const int*   idxk = (const int*)d_in[3];
    int S = in_sizes[3];
    float* out = (float*)d_out;

    cudaFuncSetAttribute(k3_attn, cudaFuncAttributeMaxDynamicSharedMemorySize, K3_SMEM_BYTES);
    cudaFuncSetAttribute(k1_M,    cudaFuncAttributeMaxDynamicSharedMemorySize, K1_SMEM_BYTES);

    // k3_attn at launch index 3 (ncu capture slot) to verify the PV-MMA change.
    // k0 (rank init) must precede k2 (rank writes).
    k1_M   <<<dim3(LL/(QT*NT), BH), 256, K1_SMEM_BYTES>>>(Q, K, idxk, S);
    k0_rinit<<<128, 256>>>();
    k2_topk<<<BH, 256>>>();
    k3_attn<<<dim3(BH, NSPLIT), 256, K3_SMEM_BYTES>>>(K, V, Q);
    k4_csum<<<dim3(NC/2, BH), 256>>>(V, 0);
    k4_csum<<<dim3(NC/2, BH), 256>>>(V, NC/2);
    k3c_combine<<<BH, 256>>>();
    k5_scan<<<dim3(NC/16, BH), 256>>>(V, out);
}

// round 17
// speedup vs baseline: 1.6807x; 1.1058x over previous
#include <cuda_runtime.h>
#include <math_constants.h>

#define BB 16
#define LL 4096
#define HH 8
#define DD 64
#define BH (BB*HH)     // 128
#define UU 45
#define NC 64
#define CLEN 64        // LL/NC

#define TQ 64          // k3: queries padded to 64 for m16 MMA slabs
#define TK 32          // k3: key tile
#define SP 68          // padded smem row stride for Q/K rows (conflict-free for QK frags)
#define SPV 72         // padded stride for V rows (72%32=8 -> conflict-free PV B frags)
#define SPS 36         // padded stride for the 64x32 score tile
#define NSPLIT 8
#define KS (LL/NSPLIT) // 512 keys per split
#define NTILES (KS/TK) // 16 tiles per split
#define CPS (KS/CLEN)  // 8 chunks per split

#define QT 64          // k1: query tile rows
#define NT 4           // k1: tiles per block (256 queries/block)
#define SN 48          // k1: padded sample count (45 real + 3 zero)

// k3 dynamic smem (floats): sQ[TQ*SP], sS[TQ*SPS], sK[2][TK*SP], sV[2][TK*SPV]
#define K3_SMEM_FLOATS (TQ*SP + TQ*SPS + 2*TK*SP + 2*TK*SPV)
#define K3_SMEM_BYTES  (K3_SMEM_FLOATS*4)
// k1 dynamic smem (floats): sQf[2][QT*SP] fp32 double-buffer; sKh,sKl [SN*SP]
#define K1_SMEM_FLOATS ((2*QT + 2*SN)*SP)
#define K1_SMEM_BYTES  (K1_SMEM_FLOATS*4)

typedef unsigned long long u64;
typedef unsigned int u32;

__device__ __forceinline__ void cpa16(unsigned sdst, const void* gsrc){
    asm volatile("cp.async.cg.shared.global [%0], [%1], 16;" :: "r"(sdst), "l"(gsrc));
}
__device__ __forceinline__ void cpa_commit(){
    asm volatile("cp.async.commit_group;");
}
__device__ __forceinline__ u32 f2tf32(float x){
    u32 r; asm("cvt.rna.tf32.f32 %0, %1;" : "=r"(r) : "f"(x)); return r;
}
// m16n8k8 tf32 MMA, D += A*B, accumulate in place
__device__ __forceinline__ void mma_tf32(float4 &d, u32 a0, u32 a1, u32 a2, u32 a3,
                                         u32 b0, u32 b1){
    asm volatile(
        "mma.sync.aligned.m16n8k8.row.col.f32.tf32.tf32.f32 "
        "{%0,%1,%2,%3}, {%4,%5,%6,%7}, {%8,%9}, {%0,%1,%2,%3};"
        : "+f"(d.x), "+f"(d.y), "+f"(d.z), "+f"(d.w)
        : "r"(a0), "r"(a1), "r"(a2), "r"(a3), "r"(b0), "r"(b1));
}

// static scratch (no allocs allowed)
__device__ float g_M[BH*LL];
__device__ int   g_Mtop[BH*UU];
__device__ int   g_rank[BH*LL];
__device__ float g_csum[BH*NC*DD];
__device__ float g_pl[BH*NSPLIT*TQ];
__device__ float g_po[(size_t)BH*NSPLIT*TQ*DD];

// ---------------- K1: M scores via 3xTF32 MMA, 4 Q-tiles/block, cp.async pipeline ----------------
__global__ __launch_bounds__(256) void k1_M(const float* __restrict__ Q,
                                            const float* __restrict__ K,
                                            const int* __restrict__ idxk, int S)
{
    extern __shared__ __align__(16) float dyn[];
    float* sQf = dyn;                 // 2 x QT*SP fp32 (double buffer)
    float* sKh = dyn + 2*QT*SP;       // SN*SP
    float* sKl = sKh + SN*SP;         // SN*SP

    __shared__ float pmax[QT][2];
    __shared__ float psum[QT][2];

    int bh = blockIdx.y;
    int b = bh >> 3, h = bh & 7;
    int q0 = blockIdx.x * (QT*NT);
    int tid = threadIdx.x;

    int lr = tid >> 4, ldv = tid & 15;
    unsigned sQ_s = (unsigned)__cvta_generic_to_shared(sQf);
    size_t qcol = ((size_t)b*LL)*HH*DD + (size_t)h*DD + ldv*4;

    #pragma unroll
    for (int t = 0; t < 4; t++) {
        int r = lr + 16*t;
        cpa16(sQ_s + (unsigned)((r*SP + ldv*4)*4),
              Q + qcol + (size_t)(q0 + r)*HH*DD);
    }
    cpa_commit();

    for (int i = tid; i < SN*DD; i += 256) {
        int s = i >> 6, d = i & 63;
        float v = 0.f;
        if (s < S) {
            int kk = idxk[s];
            v = K[(((size_t)b*LL + kk)*HH + h)*DD + d];
        }
        float sq = v * v;
        float hi = __uint_as_float(f2tf32(sq));
        float lo = __uint_as_float(f2tf32(sq - hi));
        sKh[s*SP + d] = hi;
        sKl[s*SP + d] = lo;
    }

    int wid = tid >> 5, lane = tid & 31;
    int slab = wid >> 1, nhalf = wid & 1;
    int g = lane >> 2, tig = lane & 3;
    int rowA = slab*16 + g, rowB = rowA + 8;

    const u32* Kh = (const u32*)sKh;
    const u32* Kl = (const u32*)sKl;

    for (int tile = 0; tile < NT; tile++) {
        if (tile < NT-1) {
            unsigned dstb = sQ_s + (unsigned)((((tile+1)&1)*QT*SP)*4);
            int qt = q0 + (tile+1)*QT;
            #pragma unroll
            for (int t = 0; t < 4; t++) {
                int r = lr + 16*t;
                cpa16(dstb + (unsigned)((r*SP + ldv*4)*4),
                      Q + qcol + (size_t)(qt + r)*HH*DD);
            }
            cpa_commit();
            asm volatile("cp.async.wait_group 1;");
        } else {
            asm volatile("cp.async.wait_group 0;");
        }
        __syncthreads();

        const float* sQt = sQf + (tile&1)*QT*SP;

        float4 dacc[3];
        #pragma unroll
        for (int nt = 0; nt < 3; nt++) dacc[nt] = make_float4(0.f,0.f,0.f,0.f);

        #pragma unroll
        for (int st = 0; st < 8; st++) {
            int ko = st*8;
            float af0 = sQt[rowA*SP + tig + ko];
            float af1 = sQt[rowB*SP + tig + ko];
            float af2 = sQt[rowA*SP + tig + 4 + ko];
            float af3 = sQt[rowB*SP + tig + 4 + ko];
            u32 ah0 = __float_as_uint(af0) & 0xFFFFE000u;
            u32 ah1 = __float_as_uint(af1) & 0xFFFFE000u;
            u32 ah2 = __float_as_uint(af2) & 0xFFFFE000u;
            u32 ah3 = __float_as_uint(af3) & 0xFFFFE000u;
            u32 al0 = __float_as_uint(af0 - __uint_as_float(ah0));
            u32 al1 = __float_as_uint(af1 - __uint_as_float(ah1));
            u32 al2 = __float_as_uint(af2 - __uint_as_float(ah2));
            u32 al3 = __float_as_uint(af3 - __uint_as_float(ah3));
            #pragma unroll
            for (int nt = 0; nt < 3; nt++) {
                int nrow = nhalf*24 + nt*8 + g;
                int kb = nrow*SP + ko;
                u32 bh0 = Kh[kb + tig], bh1 = Kh[kb + tig + 4];
                u32 bl0 = Kl[kb + tig], bl1 = Kl[kb + tig + 4];
                mma_tf32(dacc[nt], ah0, ah1, ah2, ah3, bh0, bh1);
                mma_tf32(dacc[nt], ah0, ah1, ah2, ah3, bl0, bl1);
                mma_tf32(dacc[nt], al0, al1, al2, al3, bh0, bh1);
            }
        }

        float mxA = -CUDART_INF_F, mxB = -CUDART_INF_F;
        float smA = 0.f, smB = 0.f;
        #pragma unroll
        for (int nt = 0; nt < 3; nt++) {
            int c0 = nhalf*24 + nt*8 + 2*tig;
            float4 d = dacc[nt];
            if (c0 < UU)     { mxA = fmaxf(mxA, d.x); mxB = fmaxf(mxB, d.z); }
            if (c0 + 1 < UU) { mxA = fmaxf(mxA, d.y); mxB = fmaxf(mxB, d.w); }
            smA += d.x + d.y;
            smB += d.z + d.w;
        }
        #pragma unroll
        for (int o = 1; o <= 2; o <<= 1) {
            mxA = fmaxf(mxA, __shfl_xor_sync(0xffffffffu, mxA, o));
            mxB = fmaxf(mxB, __shfl_xor_sync(0xffffffffu, mxB, o));
            smA += __shfl_xor_sync(0xffffffffu, smA, o);
            smB += __shfl_xor_sync(0xffffffffu, smB, o);
        }
        if (tig == 0) {
            pmax[slab*16 + g][nhalf] = mxA;      psum[slab*16 + g][nhalf] = smA;
            pmax[slab*16 + g + 8][nhalf] = mxB;  psum[slab*16 + g + 8][nhalf] = smB;
        }
        __syncthreads();
        if (tid < QT) {
            float mx = fmaxf(pmax[tid][0], pmax[tid][1]);
            float sm = psum[tid][0] + psum[tid][1];
            g_M[bh*LL + q0 + tile*QT + tid] = mx - sm * (1.0f / (float)LL);
        }
    }
}

// ---------------- K2: top-45 + rank table (init fused back in) ----------------
__global__ __launch_bounds__(256) void k2_topk()
{
    __shared__ float sM[LL];
    __shared__ float rv[8];
    __shared__ int   ri[8];
    int bh = blockIdx.x;
    for (int i = threadIdx.x; i < LL/4; i += 256) {
        ((float4*)sM)[i] = ((const float4*)(g_M + bh*LL))[i];
        ((int4*)(g_rank + bh*LL))[i] = make_int4(-1,-1,-1,-1);
    }
    __syncthreads();

    int lane = threadIdx.x & 31, wid = threadIdx.x >> 5;
    for (int it = 0; it < UU; it++) {
        float bv = -CUDART_INF_F; int bi = 0x7fffffff;
        for (int i = threadIdx.x; i < LL; i += 256) {
            float v = sM[i];
            if (v > bv || (v == bv && i < bi)) { bv = v; bi = i; }
        }
        #pragma unroll
        for (int o = 16; o > 0; o >>= 1) {
            float ov = __shfl_down_sync(0xffffffffu, bv, o);
            int   oi = __shfl_down_sync(0xffffffffu, bi, o);
            if (ov > bv || (ov == bv && oi < bi)) { bv = ov; bi = oi; }
        }
        if (lane == 0) { rv[wid] = bv; ri[wid] = bi; }
        __syncthreads();
        if (threadIdx.x == 0) {
            for (int w = 1; w < 8; w++)
                if (rv[w] > bv || (rv[w] == bv && ri[w] < bi)) { bv = rv[w]; bi = ri[w]; }
            g_Mtop[bh*UU + it] = bi;
            g_rank[bh*LL + bi] = it;
            sM[bi] = -CUDART_INF_F;
        }
        __syncthreads();
    }
}

// ---------------- K3: split-K flash (QK+PV tf32 MMA) + fused per-chunk V csum ----------------
__global__ __launch_bounds__(256, 3) void k3_attn(const float* __restrict__ Kg,
                                                  const float* __restrict__ Vg,
                                                  const float* __restrict__ Qg)
{
    extern __shared__ __align__(16) float dyn[];
    float* sQ = dyn;                          // TQ*SP
    float* sS = dyn + TQ*SP;                  // TQ*SPS
    float* sK = dyn + TQ*SP + TQ*SPS;         // 2 x TK*SP
    float* sV = sK + 2*TK*SP;                 // 2 x TK*SPV

    __shared__ int   s_qi0[TQ];
    __shared__ int   s_qi[TQ];                // sorted DESCENDING
    __shared__ int   s_ou[TQ];
    __shared__ float sLp[TQ*2];               // per-row l partials (2 N-halves)
    __shared__ float sc[4][64];               // csum partials

    int split = blockIdx.y;
    int bh = blockIdx.x;
    int b = bh >> 3, h = bh & 7;
    int tid = threadIdx.x;
    int ks = split * KS;

    if (tid < TQ) s_qi0[tid] = (tid < UU) ? g_Mtop[bh*UU + tid] : -1;
    __syncthreads();
    if (tid < TQ) {
        int qi = s_qi0[tid];
        int r = 0;
        #pragma unroll
        for (int j = 0; j < TQ; j++) {
            int qj = s_qi0[j];
            r += (qj > qi) || (qj == qi && j < tid);   // descending
        }
        s_qi[r] = qi;
        s_ou[r] = tid;
    }
    __syncthreads();

    for (int i = tid; i < TQ*16; i += 256) {
        int q = i >> 4, dv = i & 15;
        int row = s_qi[q];
        float4 v = make_float4(0.f, 0.f, 0.f, 0.f);
        if (row >= 0)
            v = ((const float4*)(Qg + (((size_t)b*LL + row)*HH + h)*DD))[dv];
        ((float4*)(sQ + q*SP))[dv] = v;
    }

    // MMA warp roles (shared by QK and PV)
    int wid2 = tid >> 5, lane = tid & 31;
    int slab = wid2 >> 1;                     // M slab (16 q rows)
    int nhalf = wid2 & 1;                     // QK: key half; PV: d half
    int g = lane >> 2, tig = lane & 3;
    int rowA = slab*16 + g, rowB = rowA + 8;

    // csum roles
    int ccol = tid & 63, crg = tid >> 6;      // col d, row-group (4 groups x 8 rows)

    __syncthreads();
    int qiA = s_qi[rowA], qiB = s_qi[rowB];
    int slab_qi = s_qi[slab*16];              // slab max (descending sort)
    int lgate_qi = (tid < TQ) ? s_qi[(tid>>4)<<4] : -1;

    float l_acc = 0.f;
    float csum_acc = 0.f;
    float4 oacc[4];
    #pragma unroll
    for (int nt = 0; nt < 4; nt++) oacc[nt] = make_float4(0.f,0.f,0.f,0.f);

    const float scale = 0.125f;

    int lr = tid >> 4, ldv = tid & 15;
    unsigned sK_s = (unsigned)__cvta_generic_to_shared(sK);
    unsigned sV_s = (unsigned)__cvta_generic_to_shared(sV);
    size_t grow = ((size_t)b*LL)*HH*DD + (size_t)h*DD + ldv*4;

    // prologue: tile 0 of this split
    #pragma unroll
    for (int t = 0; t < 2; t++) {
        int r = lr + 16*t;
        size_t go = grow + (size_t)(ks + r)*HH*DD;
        cpa16(sK_s + (unsigned)((r*SP  + ldv*4)*4), Kg + go);
        cpa16(sV_s + (unsigned)((r*SPV + ldv*4)*4), Vg + go);
    }
    cpa_commit();
    __syncthreads();

    int buf = 0;
    for (int ti = 0; ti < NTILES; ti++, buf ^= 1) {
        int t0 = ks + ti*TK;
        bool more = (ti < NTILES-1);

        if (more) {
            int tn = t0 + TK;
            unsigned kb = sK_s + (unsigned)(((buf^1)*TK*SP)*4);
            unsigned vb = sV_s + (unsigned)(((buf^1)*TK*SPV)*4);
            #pragma unroll
            for (int t = 0; t < 2; t++) {
                int r = lr + 16*t;
                size_t go = grow + (size_t)(tn + r)*HH*DD;
                cpa16(kb + (unsigned)((r*SP  + ldv*4)*4), Kg + go);
                cpa16(vb + (unsigned)((r*SPV + ldv*4)*4), Vg + go);
            }
            cpa_commit();
            asm volatile("cp.async.wait_group 1;");
        } else {
            asm volatile("cp.async.wait_group 0;");
        }
        __syncthreads();

        const float* cK = sK + buf*TK*SP;
        const float* cV = sV + buf*TK*SPV;
        bool sact = (slab_qi >= t0);          // auto-false once t0 > maxq

        // ---------- QK via tf32 MMA ----------
        if (sact) {
            const u32* sQu = (const u32*)sQ;
            const u32* cKu = (const u32*)cK;
            float4 d0 = make_float4(0.f,0.f,0.f,0.f);
            float4 d1 = make_float4(0.f,0.f,0.f,0.f);
            #pragma unroll
            for (int st = 0; st < 8; st++) {
                int ko = st*8;
                u32 a0 = sQu[rowA*SP + tig + ko];
                u32 a1 = sQu[rowB*SP + tig + ko];
                u32 a2 = sQu[rowA*SP + tig + 4 + ko];
                u32 a3 = sQu[rowB*SP + tig + 4 + ko];
                int kn0 = (nhalf*16 + g)*SP + tig + ko;
                int kn1 = (nhalf*16 + 8 + g)*SP + tig + ko;
                u32 b00 = cKu[kn0],     b01 = cKu[kn0 + 4];
                u32 b10 = cKu[kn1],     b11 = cKu[kn1 + 4];
                mma_tf32(d0, a0, a1, a2, a3, b00, b01);
                mma_tf32(d1, a0, a1, a2, a3, b10, b11);
            }
            float rsumA = 0.f, rsumB = 0.f;
            #pragma unroll
            for (int nt = 0; nt < 2; nt++) {
                float4 d = nt ? d1 : d0;
                int c0 = nhalf*16 + nt*8 + 2*tig;
                int k0g = t0 + c0;
                float pA0 = (k0g   <= qiA) ? __expf(d.x * scale) : 0.f;
                float pA1 = (k0g+1 <= qiA) ? __expf(d.y * scale) : 0.f;
                float pB0 = (k0g   <= qiB) ? __expf(d.z * scale) : 0.f;
                float pB1 = (k0g+1 <= qiB) ? __expf(d.w * scale) : 0.f;
                *(float2*)(sS + rowA*SPS + c0) = make_float2(pA0, pA1);
                *(float2*)(sS + rowB*SPS + c0) = make_float2(pB0, pB1);
                rsumA += pA0 + pA1;
                rsumB += pB0 + pB1;
            }
            rsumA += __shfl_xor_sync(0xffffffffu, rsumA, 1);
            rsumA += __shfl_xor_sync(0xffffffffu, rsumA, 2);
            rsumB += __shfl_xor_sync(0xffffffffu, rsumB, 1);
            rsumB += __shfl_xor_sync(0xffffffffu, rsumB, 2);
            if (tig == 0) {
                sLp[rowA*2 + nhalf] = rsumA;
                sLp[rowB*2 + nhalf] = rsumB;
            }
        }
        __syncthreads();    // sS + sLp visible

        // ---------- l accumulation ----------
        if (tid < TQ && lgate_qi >= t0)
            l_acc += sLp[tid*2] + sLp[tid*2 + 1];

        // ---------- PV via tf32 MMA ----------
        if (sact) {
            const u32* sSu = (const u32*)sS;
            const u32* cVu = (const u32*)cV;
            #pragma unroll
            for (int ko = 0; ko < TK; ko += 8) {
                u32 a0 = sSu[rowA*SPS + tig + ko];
                u32 a1 = sSu[rowB*SPS + tig + ko];
                u32 a2 = sSu[rowA*SPS + tig + 4 + ko];
                u32 a3 = sSu[rowB*SPS + tig + 4 + ko];
                #pragma unroll
                for (int nt = 0; nt < 4; nt++) {
                    int dcol = nhalf*32 + nt*8 + g;
                    u32 b0 = cVu[(ko + tig)*SPV + dcol];
                    u32 b1 = cVu[(ko + tig + 4)*SPV + dcol];
                    mma_tf32(oacc[nt], a0, a1, a2, a3, b0, b1);
                }
            }
        }

        // ---------- fused chunk csum (always) ----------
        #pragma unroll
        for (int rr = 0; rr < 8; rr++)
            csum_acc += cV[(crg + rr*4)*SPV + ccol];
        if (ti & 1) sc[crg][ccol] = csum_acc;

        __syncthreads();    // buffer + sS reads done; sc visible

        if (ti & 1) {
            if (tid < 64) {
                int c = split*CPS + (ti >> 1);
                g_csum[(bh*NC + c)*DD + tid] =
                    sc[0][tid] + sc[1][tid] + sc[2][tid] + sc[3][tid];
            }
            csum_acc = 0.f;
        }
        // sc reuse protected by next iteration's top __syncthreads
    }

    // ---- write partials from MMA fragments ----
    int pbase = (bh*NSPLIT + split)*TQ;
    int ouA = s_ou[rowA], ouB = s_ou[rowB];
    #pragma unroll
    for (int nt = 0; nt < 4; nt++) {
        int d = nhalf*32 + nt*8 + 2*tig;
        if (ouA < UU)
            *(float2*)(g_po + (size_t)(pbase + ouA)*DD + d) = make_float2(oacc[nt].x, oacc[nt].y);
        if (ouB < UU)
            *(float2*)(g_po + (size_t)(pbase + ouB)*DD + d) = make_float2(oacc[nt].z, oacc[nt].w);
    }
    if (tid < TQ && s_ou[tid] < UU)
        g_pl[pbase + s_ou[tid]] = l_acc;
}

// ---------------- K5: scan + scatter with inline split-combine ----------------
__global__ __launch_bounds__(256) void k5_scan(const float* __restrict__ Vg,
                                               float* __restrict__ out)
{
    __shared__ int srank[1024];
    int bh = blockIdx.y, b = bh >> 3, h = bh & 7;
    int qd = threadIdx.x & 15, cl = threadIdx.x >> 4;
    int c = blockIdx.x * 16 + cl;
    int base_l = blockIdx.x * 1024;

    for (int i = threadIdx.x; i < 1024; i += 256)
        srank[i] = g_rank[bh*LL + base_l + i];
    __syncthreads();

    float4 acc = make_float4(0.f, 0.f, 0.f, 0.f);
    for (int cc = 0; cc < c; cc++) {
        float4 v = ((const float4*)(g_csum + (bh*NC + cc)*DD))[qd];
        acc.x += v.x; acc.y += v.y; acc.z += v.z; acc.w += v.w;
    }

    int l0 = c * CLEN;
    #pragma unroll 4
    for (int j = 0; j < CLEN; j++) {
        int l = l0 + j;
        float4 v = ((const float4*)(Vg + (((size_t)b*LL + l)*HH + h)*DD))[qd];
        acc.x += v.x; acc.y += v.y; acc.z += v.z; acc.w += v.w;
        float4 o = acc;
        int r = srank[l - base_l];
        if (r >= 0) {
            // inline combine: sum 8 split partials, normalize by total l
            float lt = 0.f;
            float4 a = make_float4(0.f, 0.f, 0.f, 0.f);
            #pragma unroll
            for (int s = 0; s < NSPLIT; s++) {
                int pb = (bh*NSPLIT + s)*TQ + r;
                lt += g_pl[pb];
                float4 p = ((const float4*)(g_po + (size_t)pb*DD))[qd];
                a.x += p.x; a.y += p.y; a.z += p.z; a.w += p.w;
            }
            float inv = 1.f / lt;
            o = make_float4(a.x*inv, a.y*inv, a.z*inv, a.w*inv);
        }
        ((float4*)(out + (((size_t)b*LL + l)*HH + h)*DD))[qd] = o;
    }
}

extern "C" void kernel_launch(void* const* d_in, const int* in_sizes, int n_in,
                              void* d_out, int out_size)
{
    const float* Q    = (const float*)d_in[0];
    const float* K    = (const float*)d_in[1];
    const float* V    = (const float*)d_in[2];
    const int*   idxk = (const int*)d_in[3];
    int S = in_sizes[3];
    float* out = (float*)d_out;

    cudaFuncSetAttribute(k3_attn, cudaFuncAttributeMaxDynamicSharedMemorySize, K3_SMEM_BYTES);
    cudaFuncSetAttribute(k1_M,    cudaFuncAttributeMaxDynamicSharedMemorySize, K1_SMEM_BYTES);

    // 4 kernels total; k5 sits at the ncu capture slot (4th launch).
    k1_M   <<<dim3(LL/(QT*NT), BH), 256, K1_SMEM_BYTES>>>(Q, K, idxk, S);
    k2_topk<<<BH, 256>>>();
    k3_attn<<<dim3(BH, NSPLIT), 256, K3_SMEM_BYTES>>>(K, V, Q);
    k5_scan<<<dim3(NC/16, BH), 256>>>(V, out);
}